// round 7
// baseline (speedup 1.0000x reference)
#include <cuda_runtime.h>
#include <cuda_bf16.h>
#include <cstdint>

#define BATCH 4
#define CDIM  256
#define NPIX  4096
typedef __nv_bfloat16 bf16;

#define CN ((size_t)BATCH * NPIX * CDIM)      // 4,194,304
#define NN ((size_t)BATCH * NPIX * NPIX)      // 67,108,864

// ---------------------------------------------------------------------------
// Device scratch
// ---------------------------------------------------------------------------
__device__ bf16  g_FcT_h[CN], g_FcT_l[CN];    // F_c transposed [b][p][c]
__device__ bf16  g_FsT_h[CN], g_FsT_l[CN];
__device__ bf16  g_wf_h[CDIM*CDIM], g_wf_l[CDIM*CDIM];
__device__ bf16  g_wg_h[CDIM*CDIM], g_wg_l[CDIM*CDIM];
__device__ bf16  g_wh_h[CDIM*CDIM], g_wh_l[CDIM*CDIM];
__device__ bf16  g_wo_h[CDIM*CDIM], g_wo_l[CDIM*CDIM];
__device__ bf16  g_Fq_h[CN], g_Fq_l[CN];      // [b][i][c]
__device__ bf16  g_G_h [CN], g_G_l [CN];      // [b][j][c]
__device__ bf16  g_Hv_h[CN], g_Hv_l[CN];      // [b][c][j]
__device__ bf16  g_R_h [CN], g_R_l [CN];      // [b][i][c]
__device__ float g_S[NN];                     // attention logits fp32
__device__ float g_stM[(size_t)BATCH * 32 * NPIX];
__device__ float g_stS[(size_t)BATCH * 32 * NPIX];
__device__ float g_rowM[(size_t)BATCH * NPIX];
__device__ float g_rowIL[(size_t)BATCH * NPIX];

// ---------------------------------------------------------------------------
// PTX helpers (sm_80-level only)
// ---------------------------------------------------------------------------
__device__ __forceinline__ uint32_t smem_u32(const void* p) {
    uint32_t a;
    asm("{ .reg .u64 t; cvta.to.shared.u64 t, %1; cvt.u32.u64 %0, t; }" : "=r"(a) : "l"(p));
    return a;
}
#define CPA(s, g) asm volatile("cp.async.cg.shared.global [%0], [%1], 16;" :: "r"(s), "l"(g) : "memory")
#define CPC()     asm volatile("cp.async.commit_group;" ::: "memory")
#define CPW(n)    asm volatile("cp.async.wait_group %0;" :: "n"(n) : "memory")

__device__ __forceinline__ void ldsm4(uint32_t* r, uint32_t a) {
    asm volatile("ldmatrix.sync.aligned.m8n8.x4.shared.b16 {%0,%1,%2,%3}, [%4];"
        : "=r"(r[0]), "=r"(r[1]), "=r"(r[2]), "=r"(r[3]) : "r"(a));
}
__device__ __forceinline__ void ldsm2(uint32_t* r, uint32_t a) {
    asm volatile("ldmatrix.sync.aligned.m8n8.x2.shared.b16 {%0,%1}, [%2];"
        : "=r"(r[0]), "=r"(r[1]) : "r"(a));
}
__device__ __forceinline__ void mma_bf16(float* c, const uint32_t* a, const uint32_t* b) {
    asm volatile("mma.sync.aligned.m16n8k16.row.col.f32.bf16.bf16.f32 "
        "{%0,%1,%2,%3}, {%4,%5,%6,%7}, {%8,%9}, {%0,%1,%2,%3};"
        : "+f"(c[0]), "+f"(c[1]), "+f"(c[2]), "+f"(c[3])
        : "r"(a[0]), "r"(a[1]), "r"(a[2]), "r"(a[3]), "r"(b[0]), "r"(b[1]));
}
__device__ __forceinline__ void split2(float x, bf16& h, bf16& l) {
    h = __float2bfloat16(x);
    l = __float2bfloat16(x - __bfloat162float(h));
}

// ---------------------------------------------------------------------------
// GEMM: D[m,n] = sum_k A[m,k]*B[n,k]; K-contiguous bf16 hi/lo operands.
// CTA 128x128, BK=32, double-buffered cp.async, 8 warps, 2 CTAs/SM.
// MMA issue is PASS-MAJOR within j-pairs: same-accumulator MMAs are
// separated by 8 independent MMAs -> no RAW chain stalls.
// EPI:   0 = fp32 [m][n] (+bias), 1 = bf16 split [m][n], 2 = split transposed
// STATS: epilogue emits per-(row, n-tile) max & sumexp           (G4)
// FUSEB: B tile built in-kernel from fp32 S staged via cp.async   (G5)
// ---------------------------------------------------------------------------
#define RSB      80
#define TILE_SB  (128 * RSB)     // 10240
#define STAGE_SB (4 * TILE_SB)   // 40960
#define SF_ROW   144
#define SF_SB    (128 * SF_ROW)  // 18432
#define DSMEM    (2 * STAGE_SB)           // 81920
#define DSMEM_F  (2 * STAGE_SB + SF_SB)   // 100352

template <int EPI, bool STATS, bool FUSEB>
__global__ void __launch_bounds__(256, 2)
mma_gemm(const bf16* __restrict__ Ah_, const bf16* __restrict__ Al_,
         const bf16* __restrict__ Bh_, const bf16* __restrict__ Bl_,
         int K, int lda, int ldb, int ldo,
         long long sA, long long sB, long long sO,
         const float* __restrict__ bias,
         float* __restrict__ outF, bf16* __restrict__ oH, bf16* __restrict__ oL,
         const float* __restrict__ Sfp, const float* __restrict__ rowM,
         const float* __restrict__ rowIL,
         float* __restrict__ stM, float* __restrict__ stS)
{
    extern __shared__ char smem[];
    const uint32_t sb = smem_u32(smem);
    const int tid = threadIdx.x;
    const int lane = tid & 31, wid = tid >> 5;
    const int wm = wid >> 2, wn = wid & 3;        // 2 x 4 warp grid
    const int z = blockIdx.z;
    const int m0 = blockIdx.y * 128, n0 = blockIdx.x * 128;

    const bf16* pT[4] = {Ah_ + (size_t)z * sA, Al_ + (size_t)z * sA,
                         FUSEB ? nullptr : Bh_ + (size_t)z * sB,
                         FUSEB ? nullptr : Bl_ + (size_t)z * sB};
    const int nk = K / 32;

    const int r0 = tid >> 2, c0 = tid & 3;
    const int r1 = r0 + 64;

    auto issueA = [&](int kc) {
        if (kc >= nk) return;
        const uint32_t s0 = sb + (kc & 1) * STAGE_SB;
#pragma unroll
        for (int t = 0; t < (FUSEB ? 2 : 4); ++t) {
            const int ld = (t < 2) ? lda : ldb;
            const int base = (t < 2) ? m0 : n0;
            const bf16* g0 = pT[t] + (size_t)(base + r0) * ld + kc * 32 + c0 * 8;
            const bf16* g1 = pT[t] + (size_t)(base + r1) * ld + kc * 32 + c0 * 8;
            CPA(s0 + t * TILE_SB + r0 * RSB + c0 * 16, g0);
            CPA(s0 + t * TILE_SB + r1 * RSB + c0 * 16, g1);
        }
    };

    // FUSEB: per-thread row of the S tile
    const int pr = tid >> 1, jh = tid & 1;
    const uint32_t sf = sb + 2 * STAGE_SB;
    float mrow = 0.f, il = 0.f;
    const float* Srow = nullptr;
    if (FUSEB) {
        Srow = Sfp + (size_t)z * sB + (size_t)(n0 + pr) * ldb;
        mrow = rowM [(size_t)z * NPIX + n0 + pr];
        il   = rowIL[(size_t)z * NPIX + n0 + pr];
    }
    auto issueS = [&](int kc) {
        if (kc >= nk) return;
        const uint32_t d = sf + pr * SF_ROW + jh * 64;
        const float* g = Srow + kc * 32 + jh * 16;
#pragma unroll
        for (int q = 0; q < 4; ++q) CPA(d + q * 16, g + q * 4);
    };
    auto convB = [&](int kc) {
        const uint32_t s0 = sb + (kc & 1) * STAGE_SB;
        const float* Sf = (const float*)(smem + 2 * STAGE_SB + pr * SF_ROW + jh * 64);
        const uint32_t dH = s0 + 2 * TILE_SB + pr * RSB + jh * 32;
        const uint32_t dL = s0 + 3 * TILE_SB + pr * RSB + jh * 32;
#pragma unroll
        for (int v = 0; v < 2; ++v) {
            uint32_t hw[4], lw[4];
#pragma unroll
            for (int q = 0; q < 4; ++q) {
                float x0 = Sf[v * 8 + q * 2];
                float x1 = Sf[v * 8 + q * 2 + 1];
                float p0 = __expf(x0 - mrow) * il;
                float p1 = __expf(x1 - mrow) * il;
                bf16 h0, l0, h1, l1;
                split2(p0, h0, l0); split2(p1, h1, l1);
                __nv_bfloat162 hp(h0, h1), lp(l0, l1);
                hw[q] = *(uint32_t*)&hp; lw[q] = *(uint32_t*)&lp;
            }
            asm volatile("st.shared.v4.b32 [%0], {%1,%2,%3,%4};"
                :: "r"(dH + v * 16), "r"(hw[0]), "r"(hw[1]), "r"(hw[2]), "r"(hw[3]) : "memory");
            asm volatile("st.shared.v4.b32 [%0], {%1,%2,%3,%4};"
                :: "r"(dL + v * 16), "r"(lw[0]), "r"(lw[1]), "r"(lw[2]), "r"(lw[3]) : "memory");
        }
    };

    float acc[4][4][4];
#pragma unroll
    for (int i = 0; i < 4; ++i)
#pragma unroll
        for (int j = 0; j < 4; ++j)
#pragma unroll
            for (int q = 0; q < 4; ++q) acc[i][j][q] = 0.f;

    issueA(0); if (FUSEB) issueS(0); CPC();
    issueA(1); CPC();

    const int aRow = lane & 15;
    const int aKB  = (lane >> 4) * 16;
    const int bRow = lane & 7;
    const int bKB  = ((lane >> 3) & 1) * 16;

    for (int kc = 0; kc < nk; ++kc) {
        CPW(1);
        if (FUSEB) convB(kc);
        __syncthreads();

        const uint32_t s0 = sb + (kc & 1) * STAGE_SB;
        const uint32_t aH = s0, aL = s0 + TILE_SB;
        const uint32_t bH = s0 + 2 * TILE_SB, bL = s0 + 3 * TILE_SB;
#pragma unroll
        for (int ks = 0; ks < 2; ++ks) {
            uint32_t Af[2][4][4];
#pragma unroll
            for (int i = 0; i < 4; ++i) {
                const uint32_t off = (uint32_t)(wm * 64 + i * 16 + aRow) * RSB + ks * 32 + aKB;
                ldsm4(Af[0][i], aH + off);
                ldsm4(Af[1][i], aL + off);
            }
            // j-pairs, pass-major: same-acc MMAs are 8 apart
#pragma unroll
            for (int jp = 0; jp < 2; ++jp) {
                uint32_t Bf[2][2][2];
#pragma unroll
                for (int jj = 0; jj < 2; ++jj) {
                    const int j = jp * 2 + jj;
                    const uint32_t off = (uint32_t)(wn * 32 + j * 8 + bRow) * RSB + ks * 32 + bKB;
                    ldsm2(Bf[0][jj], bH + off);
                    ldsm2(Bf[1][jj], bL + off);
                }
#pragma unroll
                for (int p = 0; p < 3; ++p) {
                    const int pa = (p == 2) ? 1 : 0;   // lo A on pass 2
                    const int pb = (p == 1) ? 1 : 0;   // lo B on pass 1
#pragma unroll
                    for (int jj = 0; jj < 2; ++jj)
#pragma unroll
                        for (int i = 0; i < 4; ++i)
                            mma_bf16(acc[i][jp * 2 + jj], Af[pa][i], Bf[pb][jj]);
                }
            }
        }
        __syncthreads();
        if (FUSEB) { issueS(kc + 1); CPC(); issueA(kc + 2); CPC(); }
        else       { issueA(kc + 2); CPC(); }
    }

    // ---- epilogue: stage D (+bias on m) through smem ----
    float* stg = (float*)smem;                   // [128][132]
    const int gid = lane >> 2, tig = lane & 3;
#pragma unroll
    for (int i = 0; i < 4; ++i) {
        const int ml = wm * 64 + i * 16 + gid;
        const float bv0 = bias ? bias[m0 + ml] : 0.f;
        const float bv8 = bias ? bias[m0 + ml + 8] : 0.f;
#pragma unroll
        for (int j = 0; j < 4; ++j) {
            const int nl = wn * 32 + j * 8 + tig * 2;
            stg[ml * 132 + nl]           = acc[i][j][0] + bv0;
            stg[ml * 132 + nl + 1]       = acc[i][j][1] + bv0;
            stg[(ml + 8) * 132 + nl]     = acc[i][j][2] + bv8;
            stg[(ml + 8) * 132 + nl + 1] = acc[i][j][3] + bv8;
        }
    }
    __syncthreads();

    const int row = tid >> 1, half = tid & 1;
    if (EPI == 0) {
        float* dst = outF + (size_t)z * sO + (size_t)(m0 + row) * ldo + n0 + half * 64;
        const float4* s4 = (const float4*)&stg[row * 132 + half * 64];
#pragma unroll
        for (int i = 0; i < 16; ++i) ((float4*)dst)[i] = s4[i];
    } else if (EPI == 1) {
        const size_t base = (size_t)z * sO + (size_t)(m0 + row) * ldo + n0 + half * 64;
#pragma unroll
        for (int v = 0; v < 8; ++v) {
            uint32_t hw[4], lw[4];
#pragma unroll
            for (int q = 0; q < 4; ++q) {
                float x0 = stg[row * 132 + half * 64 + v * 8 + q * 2];
                float x1 = stg[row * 132 + half * 64 + v * 8 + q * 2 + 1];
                bf16 h0, l0, h1, l1;
                split2(x0, h0, l0); split2(x1, h1, l1);
                __nv_bfloat162 hp(h0, h1), lp(l0, l1);
                hw[q] = *(uint32_t*)&hp; lw[q] = *(uint32_t*)&lp;
            }
            *(uint4*)(oH + base + v * 8) = make_uint4(hw[0], hw[1], hw[2], hw[3]);
            *(uint4*)(oL + base + v * 8) = make_uint4(lw[0], lw[1], lw[2], lw[3]);
        }
    } else {
        const int n = row, mh = half * 64;
        const size_t base = (size_t)z * sO + (size_t)(n0 + n) * ldo + m0 + mh;
#pragma unroll
        for (int v = 0; v < 8; ++v) {
            uint32_t hw[4], lw[4];
#pragma unroll
            for (int q = 0; q < 4; ++q) {
                float x0 = stg[(mh + v * 8 + q * 2) * 132 + n];
                float x1 = stg[(mh + v * 8 + q * 2 + 1) * 132 + n];
                bf16 h0, l0, h1, l1;
                split2(x0, h0, l0); split2(x1, h1, l1);
                __nv_bfloat162 hp(h0, h1), lp(l0, l1);
                hw[q] = *(uint32_t*)&hp; lw[q] = *(uint32_t*)&lp;
            }
            *(uint4*)(oH + base + v * 8) = make_uint4(hw[0], hw[1], hw[2], hw[3]);
            *(uint4*)(oL + base + v * 8) = make_uint4(lw[0], lw[1], lw[2], lw[3]);
        }
    }

    if (STATS) {
        float mx = -3.0e38f;
#pragma unroll
        for (int q = 0; q < 64; ++q) mx = fmaxf(mx, stg[row * 132 + half * 64 + q]);
        mx = fmaxf(mx, __shfl_xor_sync(0xffffffffu, mx, 1));
        float s = 0.f;
#pragma unroll
        for (int q = 0; q < 64; ++q) s += __expf(stg[row * 132 + half * 64 + q] - mx);
        s += __shfl_xor_sync(0xffffffffu, s, 1);
        if (half == 0) {
            size_t o = ((size_t)z * 32 + blockIdx.x) * NPIX + m0 + row;
            stM[o] = mx; stS[o] = s;
        }
    }
}

// ---------------------------------------------------------------------------
__global__ void __launch_bounds__(256)
combine_stats(const float* __restrict__ stM, const float* __restrict__ stS,
              float* __restrict__ rowM, float* __restrict__ rowIL)
{
    const int idx = blockIdx.x * 256 + threadIdx.x;
    if (idx >= BATCH * NPIX) return;
    const int z = idx >> 12, i = idx & (NPIX - 1);
    float m = -3.0e38f;
#pragma unroll 4
    for (int t = 0; t < 32; ++t)
        m = fmaxf(m, stM[((size_t)z * 32 + t) * NPIX + i]);
    float l = 0.f;
#pragma unroll 4
    for (int t = 0; t < 32; ++t) {
        size_t o = ((size_t)z * 32 + t) * NPIX + i;
        l += stS[o] * __expf(stM[o] - m);
    }
    rowM[idx] = m;
    rowIL[idx] = 1.0f / l;
}

// ---------------------------------------------------------------------------
__global__ void __launch_bounds__(256)
tsplit_both(const float* __restrict__ Fc, const float* __restrict__ Fs,
            bf16* __restrict__ ohc, bf16* __restrict__ olc,
            bf16* __restrict__ ohs, bf16* __restrict__ ols)
{
    __shared__ float t[32][33];
    const int zz = blockIdx.z;
    const int b = zz & 3;
    const float* X = (zz < 4) ? Fc : Fs;
    bf16* oh = (zz < 4) ? ohc : ohs;
    bf16* ol = (zz < 4) ? olc : ols;
    const int pb = blockIdx.x * 32, cb = blockIdx.y * 32;
    const float* src = X + (size_t)b * CDIM * NPIX;
#pragma unroll
    for (int j = 0; j < 4; ++j) {
        int c = cb + threadIdx.y + j * 8;
        t[threadIdx.y + j * 8][threadIdx.x] = src[(size_t)c * NPIX + pb + threadIdx.x];
    }
    __syncthreads();
#pragma unroll
    for (int j = 0; j < 4; ++j) {
        int p = pb + threadIdx.y + j * 8;
        float v = t[threadIdx.x][threadIdx.y + j * 8];
        size_t o = (size_t)b * NPIX * CDIM + (size_t)p * CDIM + cb + threadIdx.x;
        bf16 h, l; split2(v, h, l);
        oh[o] = h; ol[o] = l;
    }
}

__global__ void __launch_bounds__(256)
wsplit_all(const float* __restrict__ w0, const float* __restrict__ w1,
           const float* __restrict__ w2, const float* __restrict__ w3,
           bf16* __restrict__ h0, bf16* __restrict__ l0,
           bf16* __restrict__ h1, bf16* __restrict__ l1,
           bf16* __restrict__ h2, bf16* __restrict__ l2,
           bf16* __restrict__ h3, bf16* __restrict__ l3)
{
    const float* w = (blockIdx.y == 0) ? w0 : (blockIdx.y == 1) ? w1 : (blockIdx.y == 2) ? w2 : w3;
    bf16* hh = (blockIdx.y == 0) ? h0 : (blockIdx.y == 1) ? h1 : (blockIdx.y == 2) ? h2 : h3;
    bf16* ll = (blockIdx.y == 0) ? l0 : (blockIdx.y == 1) ? l1 : (blockIdx.y == 2) ? l2 : l3;
    int i = blockIdx.x * 256 + threadIdx.x;
    if (i < CDIM * CDIM) { bf16 a, b; split2(w[i], a, b); hh[i] = a; ll[i] = b; }
}

// ---------------------------------------------------------------------------
extern "C" void kernel_launch(void* const* d_in, const int* in_sizes, int n_in,
                              void* d_out, int out_size)
{
    const float* F_c = (const float*)d_in[0];
    const float* F_s = (const float*)d_in[1];
    const float* w_f = (const float*)d_in[2];
    const float* b_f = (const float*)d_in[3];
    const float* w_g = (const float*)d_in[4];
    const float* b_g = (const float*)d_in[5];
    const float* w_h = (const float*)d_in[6];
    const float* b_h = (const float*)d_in[7];
    const float* w_o = (const float*)d_in[8];
    const float* b_o = (const float*)d_in[9];
    float* out = (float*)d_out;

    bf16 *FcTh, *FcTl, *FsTh, *FsTl, *wfh, *wfl, *wgh, *wgl, *whh, *whl, *woh, *wol;
    bf16 *Fqh, *Fql, *Gh, *Gl, *Hvh, *Hvl, *Rh, *Rl;
    float *S, *stM, *stS, *rowM, *rowIL;
    cudaGetSymbolAddress((void**)&FcTh, g_FcT_h); cudaGetSymbolAddress((void**)&FcTl, g_FcT_l);
    cudaGetSymbolAddress((void**)&FsTh, g_FsT_h); cudaGetSymbolAddress((void**)&FsTl, g_FsT_l);
    cudaGetSymbolAddress((void**)&wfh, g_wf_h);   cudaGetSymbolAddress((void**)&wfl, g_wf_l);
    cudaGetSymbolAddress((void**)&wgh, g_wg_h);   cudaGetSymbolAddress((void**)&wgl, g_wg_l);
    cudaGetSymbolAddress((void**)&whh, g_wh_h);   cudaGetSymbolAddress((void**)&whl, g_wh_l);
    cudaGetSymbolAddress((void**)&woh, g_wo_h);   cudaGetSymbolAddress((void**)&wol, g_wo_l);
    cudaGetSymbolAddress((void**)&Fqh, g_Fq_h);   cudaGetSymbolAddress((void**)&Fql, g_Fq_l);
    cudaGetSymbolAddress((void**)&Gh,  g_G_h);    cudaGetSymbolAddress((void**)&Gl,  g_G_l);
    cudaGetSymbolAddress((void**)&Hvh, g_Hv_h);   cudaGetSymbolAddress((void**)&Hvl, g_Hv_l);
    cudaGetSymbolAddress((void**)&Rh,  g_R_h);    cudaGetSymbolAddress((void**)&Rl,  g_R_l);
    cudaGetSymbolAddress((void**)&S,   g_S);
    cudaGetSymbolAddress((void**)&stM, g_stM);    cudaGetSymbolAddress((void**)&stS, g_stS);
    cudaGetSymbolAddress((void**)&rowM, g_rowM);  cudaGetSymbolAddress((void**)&rowIL, g_rowIL);

    cudaFuncSetAttribute(mma_gemm<2,false,false>, cudaFuncAttributeMaxDynamicSharedMemorySize, DSMEM);
    cudaFuncSetAttribute(mma_gemm<1,false,false>, cudaFuncAttributeMaxDynamicSharedMemorySize, DSMEM);
    cudaFuncSetAttribute(mma_gemm<0,true ,false>, cudaFuncAttributeMaxDynamicSharedMemorySize, DSMEM);
    cudaFuncSetAttribute(mma_gemm<2,false,true >, cudaFuncAttributeMaxDynamicSharedMemorySize, DSMEM_F);
    cudaFuncSetAttribute(mma_gemm<0,false,false>, cudaFuncAttributeMaxDynamicSharedMemorySize, DSMEM);

    const long long cn = (long long)NPIX * CDIM;
    const long long nn = (long long)NPIX * NPIX;

    dim3 gConv(NPIX / 128, CDIM / 128, BATCH);   // 32 x 2 x 4
    dim3 gS(NPIX / 128, NPIX / 128, BATCH);      // 32 x 32 x 4

    wsplit_all<<<dim3(256, 4), 256>>>(w_f, w_g, w_h, w_o,
        wfh, wfl, wgh, wgl, whh, whl, woh, wol);
    tsplit_both<<<dim3(128, 8, 8), dim3(32, 8)>>>(F_c, F_s, FcTh, FcTl, FsTh, FsTl);
    // G1
    mma_gemm<2,false,false><<<gConv, 256, DSMEM>>>(wfh, wfl, FcTh, FcTl,
        CDIM, CDIM, CDIM, CDIM, 0, cn, cn, b_f, nullptr, Fqh, Fql,
        nullptr, nullptr, nullptr, nullptr, nullptr);
    // G2
    mma_gemm<2,false,false><<<gConv, 256, DSMEM>>>(wgh, wgl, FsTh, FsTl,
        CDIM, CDIM, CDIM, CDIM, 0, cn, cn, b_g, nullptr, Gh, Gl,
        nullptr, nullptr, nullptr, nullptr, nullptr);
    // G4 + stats — ncu target
    mma_gemm<0,true,false><<<gS, 256, DSMEM>>>(Fqh, Fql, Gh, Gl,
        CDIM, CDIM, CDIM, NPIX, cn, cn, nn, nullptr, S, nullptr, nullptr,
        nullptr, nullptr, nullptr, stM, stS);
    // G3
    mma_gemm<1,false,false><<<gConv, 256, DSMEM>>>(whh, whl, FsTh, FsTl,
        CDIM, CDIM, CDIM, NPIX, 0, cn, cn, b_h, nullptr, Hvh, Hvl,
        nullptr, nullptr, nullptr, nullptr, nullptr);
    // stats fold
    combine_stats<<<(BATCH * NPIX + 255) / 256, 256>>>(stM, stS, rowM, rowIL);
    // G5 fused
    mma_gemm<2,false,true><<<gConv, 256, DSMEM_F>>>(Hvh, Hvl, nullptr, nullptr,
        NPIX, NPIX, NPIX, CDIM, cn, nn, cn, nullptr, nullptr, Rh, Rl,
        S, rowM, rowIL, nullptr, nullptr);
    // G6
    mma_gemm<0,false,false><<<gConv, 256, DSMEM>>>(woh, wol, Rh, Rl,
        CDIM, CDIM, CDIM, NPIX, 0, cn, cn, b_o, out, nullptr, nullptr,
        nullptr, nullptr, nullptr, nullptr, nullptr);
}

// round 8
// speedup vs baseline: 1.2341x; 1.2341x over previous
#include <cuda_runtime.h>
#include <cuda_fp16.h>
#include <cstdint>

#define BATCH 4
#define CDIM  256
#define NPIX  4096
typedef __half fp16;

#define CN ((size_t)BATCH * NPIX * CDIM)      // 4,194,304
#define NN ((size_t)BATCH * NPIX * NPIX)      // 67,108,864

// ---------------------------------------------------------------------------
// Device scratch
// ---------------------------------------------------------------------------
__device__ fp16  g_FcT_h[CN], g_FcT_l[CN];    // F_c transposed [b][p][c]
__device__ fp16  g_FsT_h[CN], g_FsT_l[CN];
__device__ fp16  g_wf_h[CDIM*CDIM], g_wf_l[CDIM*CDIM];
__device__ fp16  g_wg_h[CDIM*CDIM], g_wg_l[CDIM*CDIM];
__device__ fp16  g_wh_h[CDIM*CDIM], g_wh_l[CDIM*CDIM];
__device__ fp16  g_wo_h[CDIM*CDIM], g_wo_l[CDIM*CDIM];
__device__ fp16  g_Fq_h[CN], g_Fq_l[CN];      // [b][i][c]
__device__ fp16  g_G_h [CN], g_G_l [CN];      // [b][j][c]
__device__ fp16  g_Hv_h[CN], g_Hv_l[CN];      // [b][c][j]
__device__ fp16  g_R_h [CN], g_R_l [CN];      // [b][i][c]
__device__ float g_S[NN];                     // attention logits fp32
__device__ float g_stM[(size_t)BATCH * 32 * NPIX];
__device__ float g_stS[(size_t)BATCH * 32 * NPIX];
__device__ float g_rowM[(size_t)BATCH * NPIX];
__device__ float g_rowIL[(size_t)BATCH * NPIX];

// ---------------------------------------------------------------------------
// PTX helpers (sm_80-level only)
// ---------------------------------------------------------------------------
__device__ __forceinline__ uint32_t smem_u32(const void* p) {
    uint32_t a;
    asm("{ .reg .u64 t; cvta.to.shared.u64 t, %1; cvt.u32.u64 %0, t; }" : "=r"(a) : "l"(p));
    return a;
}
#define CPA(s, g) asm volatile("cp.async.cg.shared.global [%0], [%1], 16;" :: "r"(s), "l"(g) : "memory")
#define CPC()     asm volatile("cp.async.commit_group;" ::: "memory")
#define CPW(n)    asm volatile("cp.async.wait_group %0;" :: "n"(n) : "memory")

__device__ __forceinline__ void ldsm4(uint32_t* r, uint32_t a) {
    asm volatile("ldmatrix.sync.aligned.m8n8.x4.shared.b16 {%0,%1,%2,%3}, [%4];"
        : "=r"(r[0]), "=r"(r[1]), "=r"(r[2]), "=r"(r[3]) : "r"(a));
}
__device__ __forceinline__ void ldsm2(uint32_t* r, uint32_t a) {
    asm volatile("ldmatrix.sync.aligned.m8n8.x2.shared.b16 {%0,%1}, [%2];"
        : "=r"(r[0]), "=r"(r[1]) : "r"(a));
}
__device__ __forceinline__ void mma_fp16(float* c, const uint32_t* a, const uint32_t* b) {
    asm volatile("mma.sync.aligned.m16n8k16.row.col.f32.f16.f16.f32 "
        "{%0,%1,%2,%3}, {%4,%5,%6,%7}, {%8,%9}, {%0,%1,%2,%3};"
        : "+f"(c[0]), "+f"(c[1]), "+f"(c[2]), "+f"(c[3])
        : "r"(a[0]), "r"(a[1]), "r"(a[2]), "r"(a[3]), "r"(b[0]), "r"(b[1]));
}
__device__ __forceinline__ void split2h(float x, fp16& h, fp16& l) {
    h = __float2half_rn(x);
    l = __float2half_rn(x - __half2float(h));
}
__device__ __forceinline__ uint32_t packsplit_h(float x0, float x1) {
    __half2 hp = __halves2half2(__float2half_rn(x0), __float2half_rn(x1));
    return *(uint32_t*)&hp;
}

// ---------------------------------------------------------------------------
// GEMM: D[m,n] = sum_k A[m,k]*B[n,k]; K-contiguous fp16 hi/lo operands.
// CTA 128x128, BK=32, double-buffered cp.async, 8 warps, 2 CTAs/SM.
// PASSES: 3 = Ah·Bh + Al·Bh + Ah·Bl (full split precision)
//         2 = Ah·Bh + Al·Bh        (A split, B single-rounded)
//         1 = Ah·Bh                (both single-rounded)
// EPI:   0 = fp32 [m][n] (+bias), 1 = fp16 split [m][n], 2 = split transposed
// STATS: epilogue emits per-(row, n-tile) max & sumexp           (G4)
// FUSEB: B (hi) tile built in-kernel from fp32 S staged via cp.async (G5)
// ---------------------------------------------------------------------------
#define RSB      80
#define TILE_SB  (128 * RSB)     // 10240
#define STAGE_SB (4 * TILE_SB)   // 40960
#define SF_ROW   144
#define SF_SB    (128 * SF_ROW)  // 18432
#define DSMEM    (2 * STAGE_SB)           // 81920
#define DSMEM_F  (2 * STAGE_SB + SF_SB)   // 100352

template <int EPI, bool STATS, bool FUSEB, int PASSES>
__global__ void __launch_bounds__(256, 2)
mma_gemm(const fp16* __restrict__ Ah_, const fp16* __restrict__ Al_,
         const fp16* __restrict__ Bh_, const fp16* __restrict__ Bl_,
         int K, int lda, int ldb, int ldo,
         long long sA, long long sB, long long sO,
         const float* __restrict__ bias,
         float* __restrict__ outF, fp16* __restrict__ oH, fp16* __restrict__ oL,
         const float* __restrict__ Sfp, const float* __restrict__ rowM,
         const float* __restrict__ rowIL,
         float* __restrict__ stM, float* __restrict__ stS)
{
    extern __shared__ char smem[];
    const uint32_t sb = smem_u32(smem);
    const int tid = threadIdx.x;
    const int lane = tid & 31, wid = tid >> 5;
    const int wm = wid >> 2, wn = wid & 3;        // 2 x 4 warp grid
    const int z = blockIdx.z;
    const int m0 = blockIdx.y * 128, n0 = blockIdx.x * 128;

    const fp16* pT[4] = {Ah_ + (size_t)z * sA,
                         (PASSES >= 2) ? Al_ + (size_t)z * sA : nullptr,
                         FUSEB ? nullptr : Bh_ + (size_t)z * sB,
                         (!FUSEB && PASSES >= 3) ? Bl_ + (size_t)z * sB : nullptr};
    const int nk = K / 32;

    const int r0 = tid >> 2, c0 = tid & 3;
    const int r1 = r0 + 64;

    auto issueA = [&](int kc) {
        if (kc >= nk) return;
        const uint32_t s0 = sb + (kc & 1) * STAGE_SB;
#pragma unroll
        for (int t = 0; t < 4; ++t) {
            if (t == 1 && PASSES < 2) continue;
            if (t >= 2 && FUSEB) continue;
            if (t == 3 && PASSES < 3) continue;
            const int ld = (t < 2) ? lda : ldb;
            const int base = (t < 2) ? m0 : n0;
            const fp16* g0 = pT[t] + (size_t)(base + r0) * ld + kc * 32 + c0 * 8;
            const fp16* g1 = pT[t] + (size_t)(base + r1) * ld + kc * 32 + c0 * 8;
            CPA(s0 + t * TILE_SB + r0 * RSB + c0 * 16, g0);
            CPA(s0 + t * TILE_SB + r1 * RSB + c0 * 16, g1);
        }
    };

    // FUSEB: per-thread row of the S tile
    const int pr = tid >> 1, jh = tid & 1;
    const uint32_t sf = sb + 2 * STAGE_SB;
    float mrow = 0.f, il = 0.f;
    const float* Srow = nullptr;
    if (FUSEB) {
        Srow = Sfp + (size_t)z * sB + (size_t)(n0 + pr) * ldb;
        mrow = rowM [(size_t)z * NPIX + n0 + pr];
        il   = rowIL[(size_t)z * NPIX + n0 + pr];
    }
    auto issueS = [&](int kc) {
        if (kc >= nk) return;
        const uint32_t d = sf + pr * SF_ROW + jh * 64;
        const float* g = Srow + kc * 32 + jh * 16;
#pragma unroll
        for (int q = 0; q < 4; ++q) CPA(d + q * 16, g + q * 4);
    };
    auto convB = [&](int kc) {     // fp32 S -> P = exp(S-m)*il -> fp16 hi tile
        const uint32_t s0 = sb + (kc & 1) * STAGE_SB;
        const float* Sf = (const float*)(smem + 2 * STAGE_SB + pr * SF_ROW + jh * 64);
        const uint32_t dH = s0 + 2 * TILE_SB + pr * RSB + jh * 32;
#pragma unroll
        for (int v = 0; v < 2; ++v) {
            uint32_t hw[4];
#pragma unroll
            for (int q = 0; q < 4; ++q) {
                float p0 = __expf(Sf[v * 8 + q * 2]     - mrow) * il;
                float p1 = __expf(Sf[v * 8 + q * 2 + 1] - mrow) * il;
                hw[q] = packsplit_h(p0, p1);
            }
            asm volatile("st.shared.v4.b32 [%0], {%1,%2,%3,%4};"
                :: "r"(dH + v * 16), "r"(hw[0]), "r"(hw[1]), "r"(hw[2]), "r"(hw[3]) : "memory");
        }
    };

    float acc[4][4][4];
#pragma unroll
    for (int i = 0; i < 4; ++i)
#pragma unroll
        for (int j = 0; j < 4; ++j)
#pragma unroll
            for (int q = 0; q < 4; ++q) acc[i][j][q] = 0.f;

    issueA(0); if (FUSEB) issueS(0); CPC();
    issueA(1); CPC();

    const int aRow = lane & 15;
    const int aKB  = (lane >> 4) * 16;
    const int bRow = lane & 7;
    const int bKB  = ((lane >> 3) & 1) * 16;

    for (int kc = 0; kc < nk; ++kc) {
        CPW(1);
        if (FUSEB) convB(kc);
        __syncthreads();

        const uint32_t s0 = sb + (kc & 1) * STAGE_SB;
        const uint32_t aH = s0, aL = s0 + TILE_SB;
        const uint32_t bH = s0 + 2 * TILE_SB, bL = s0 + 3 * TILE_SB;
#pragma unroll
        for (int ks = 0; ks < 2; ++ks) {
            uint32_t Af[2][4][4];
#pragma unroll
            for (int i = 0; i < 4; ++i) {
                const uint32_t off = (uint32_t)(wm * 64 + i * 16 + aRow) * RSB + ks * 32 + aKB;
                ldsm4(Af[0][i], aH + off);
                if (PASSES >= 2) ldsm4(Af[1][i], aL + off);
            }
#pragma unroll
            for (int jp = 0; jp < 2; ++jp) {
                uint32_t Bf[2][2][2];
#pragma unroll
                for (int jj = 0; jj < 2; ++jj) {
                    const int j = jp * 2 + jj;
                    const uint32_t off = (uint32_t)(wn * 32 + j * 8 + bRow) * RSB + ks * 32 + bKB;
                    ldsm2(Bf[0][jj], bH + off);
                    if (PASSES >= 3) ldsm2(Bf[1][jj], bL + off);
                }
#pragma unroll
                for (int jj = 0; jj < 2; ++jj)
#pragma unroll
                    for (int i = 0; i < 4; ++i)
                        mma_fp16(acc[i][jp * 2 + jj], Af[0][i], Bf[0][jj]);
                if (PASSES >= 2)
#pragma unroll
                    for (int jj = 0; jj < 2; ++jj)
#pragma unroll
                        for (int i = 0; i < 4; ++i)
                            mma_fp16(acc[i][jp * 2 + jj], Af[1][i], Bf[0][jj]);
                if (PASSES >= 3)
#pragma unroll
                    for (int jj = 0; jj < 2; ++jj)
#pragma unroll
                        for (int i = 0; i < 4; ++i)
                            mma_fp16(acc[i][jp * 2 + jj], Af[0][i], Bf[1][jj]);
            }
        }
        __syncthreads();
        if (FUSEB) { issueS(kc + 1); CPC(); issueA(kc + 2); CPC(); }
        else       { issueA(kc + 2); CPC(); }
    }

    // ---- epilogue: stage D (+bias on m) through smem ----
    float* stg = (float*)smem;                   // [128][132]
    const int gid = lane >> 2, tig = lane & 3;
#pragma unroll
    for (int i = 0; i < 4; ++i) {
        const int ml = wm * 64 + i * 16 + gid;
        const float bv0 = bias ? bias[m0 + ml] : 0.f;
        const float bv8 = bias ? bias[m0 + ml + 8] : 0.f;
#pragma unroll
        for (int j = 0; j < 4; ++j) {
            const int nl = wn * 32 + j * 8 + tig * 2;
            stg[ml * 132 + nl]           = acc[i][j][0] + bv0;
            stg[ml * 132 + nl + 1]       = acc[i][j][1] + bv0;
            stg[(ml + 8) * 132 + nl]     = acc[i][j][2] + bv8;
            stg[(ml + 8) * 132 + nl + 1] = acc[i][j][3] + bv8;
        }
    }
    __syncthreads();

    const int row = tid >> 1, half = tid & 1;
    if (EPI == 0) {
        float* dst = outF + (size_t)z * sO + (size_t)(m0 + row) * ldo + n0 + half * 64;
        const float4* s4 = (const float4*)&stg[row * 132 + half * 64];
#pragma unroll
        for (int i = 0; i < 16; ++i) ((float4*)dst)[i] = s4[i];
    } else if (EPI == 1) {
        const size_t base = (size_t)z * sO + (size_t)(m0 + row) * ldo + n0 + half * 64;
#pragma unroll
        for (int v = 0; v < 8; ++v) {
            uint32_t hw[4], lw[4];
#pragma unroll
            for (int q = 0; q < 4; ++q) {
                float x0 = stg[row * 132 + half * 64 + v * 8 + q * 2];
                float x1 = stg[row * 132 + half * 64 + v * 8 + q * 2 + 1];
                fp16 h0, l0, h1, l1;
                split2h(x0, h0, l0); split2h(x1, h1, l1);
                __half2 hp = __halves2half2(h0, h1), lp = __halves2half2(l0, l1);
                hw[q] = *(uint32_t*)&hp; lw[q] = *(uint32_t*)&lp;
            }
            *(uint4*)(oH + base + v * 8) = make_uint4(hw[0], hw[1], hw[2], hw[3]);
            *(uint4*)(oL + base + v * 8) = make_uint4(lw[0], lw[1], lw[2], lw[3]);
        }
    } else {
        const int n = row, mh = half * 64;
        const size_t base = (size_t)z * sO + (size_t)(n0 + n) * ldo + m0 + mh;
#pragma unroll
        for (int v = 0; v < 8; ++v) {
            uint32_t hw[4], lw[4];
#pragma unroll
            for (int q = 0; q < 4; ++q) {
                float x0 = stg[(mh + v * 8 + q * 2) * 132 + n];
                float x1 = stg[(mh + v * 8 + q * 2 + 1) * 132 + n];
                fp16 h0, l0, h1, l1;
                split2h(x0, h0, l0); split2h(x1, h1, l1);
                __half2 hp = __halves2half2(h0, h1), lp = __halves2half2(l0, l1);
                hw[q] = *(uint32_t*)&hp; lw[q] = *(uint32_t*)&lp;
            }
            *(uint4*)(oH + base + v * 8) = make_uint4(hw[0], hw[1], hw[2], hw[3]);
            *(uint4*)(oL + base + v * 8) = make_uint4(lw[0], lw[1], lw[2], lw[3]);
        }
    }

    if (STATS) {
        float mx = -3.0e38f;
#pragma unroll
        for (int q = 0; q < 64; ++q) mx = fmaxf(mx, stg[row * 132 + half * 64 + q]);
        mx = fmaxf(mx, __shfl_xor_sync(0xffffffffu, mx, 1));
        float s = 0.f;
#pragma unroll
        for (int q = 0; q < 64; ++q) s += __expf(stg[row * 132 + half * 64 + q] - mx);
        s += __shfl_xor_sync(0xffffffffu, s, 1);
        if (half == 0) {
            size_t o = ((size_t)z * 32 + blockIdx.x) * NPIX + m0 + row;
            stM[o] = mx; stS[o] = s;
        }
    }
}

// ---------------------------------------------------------------------------
__global__ void __launch_bounds__(256)
combine_stats(const float* __restrict__ stM, const float* __restrict__ stS,
              float* __restrict__ rowM, float* __restrict__ rowIL)
{
    const int idx = blockIdx.x * 256 + threadIdx.x;
    if (idx >= BATCH * NPIX) return;
    const int z = idx >> 12, i = idx & (NPIX - 1);
    float m = -3.0e38f;
#pragma unroll 4
    for (int t = 0; t < 32; ++t)
        m = fmaxf(m, stM[((size_t)z * 32 + t) * NPIX + i]);
    float l = 0.f;
#pragma unroll 4
    for (int t = 0; t < 32; ++t) {
        size_t o = ((size_t)z * 32 + t) * NPIX + i;
        l += stS[o] * __expf(stM[o] - m);
    }
    rowM[idx] = m;
    rowIL[idx] = 1.0f / l;
}

// ---------------------------------------------------------------------------
__global__ void __launch_bounds__(256)
tsplit_both(const float* __restrict__ Fc, const float* __restrict__ Fs,
            fp16* __restrict__ ohc, fp16* __restrict__ olc,
            fp16* __restrict__ ohs, fp16* __restrict__ ols)
{
    __shared__ float t[32][33];
    const int zz = blockIdx.z;
    const int b = zz & 3;
    const float* X = (zz < 4) ? Fc : Fs;
    fp16* oh = (zz < 4) ? ohc : ohs;
    fp16* ol = (zz < 4) ? olc : ols;
    const int pb = blockIdx.x * 32, cb = blockIdx.y * 32;
    const float* src = X + (size_t)b * CDIM * NPIX;
#pragma unroll
    for (int j = 0; j < 4; ++j) {
        int c = cb + threadIdx.y + j * 8;
        t[threadIdx.y + j * 8][threadIdx.x] = src[(size_t)c * NPIX + pb + threadIdx.x];
    }
    __syncthreads();
#pragma unroll
    for (int j = 0; j < 4; ++j) {
        int p = pb + threadIdx.y + j * 8;
        float v = t[threadIdx.x][threadIdx.y + j * 8];
        size_t o = (size_t)b * NPIX * CDIM + (size_t)p * CDIM + cb + threadIdx.x;
        fp16 h, l; split2h(v, h, l);
        oh[o] = h; ol[o] = l;
    }
}

__global__ void __launch_bounds__(256)
wsplit_all(const float* __restrict__ w0, const float* __restrict__ w1,
           const float* __restrict__ w2, const float* __restrict__ w3,
           fp16* __restrict__ h0, fp16* __restrict__ l0,
           fp16* __restrict__ h1, fp16* __restrict__ l1,
           fp16* __restrict__ h2, fp16* __restrict__ l2,
           fp16* __restrict__ h3, fp16* __restrict__ l3)
{
    const float* w = (blockIdx.y == 0) ? w0 : (blockIdx.y == 1) ? w1 : (blockIdx.y == 2) ? w2 : w3;
    fp16* hh = (blockIdx.y == 0) ? h0 : (blockIdx.y == 1) ? h1 : (blockIdx.y == 2) ? h2 : h3;
    fp16* ll = (blockIdx.y == 0) ? l0 : (blockIdx.y == 1) ? l1 : (blockIdx.y == 2) ? l2 : l3;
    int i = blockIdx.x * 256 + threadIdx.x;
    if (i < CDIM * CDIM) { fp16 a, b; split2h(w[i], a, b); hh[i] = a; ll[i] = b; }
}

// ---------------------------------------------------------------------------
extern "C" void kernel_launch(void* const* d_in, const int* in_sizes, int n_in,
                              void* d_out, int out_size)
{
    const float* F_c = (const float*)d_in[0];
    const float* F_s = (const float*)d_in[1];
    const float* w_f = (const float*)d_in[2];
    const float* b_f = (const float*)d_in[3];
    const float* w_g = (const float*)d_in[4];
    const float* b_g = (const float*)d_in[5];
    const float* w_h = (const float*)d_in[6];
    const float* b_h = (const float*)d_in[7];
    const float* w_o = (const float*)d_in[8];
    const float* b_o = (const float*)d_in[9];
    float* out = (float*)d_out;

    fp16 *FcTh, *FcTl, *FsTh, *FsTl, *wfh, *wfl, *wgh, *wgl, *whh, *whl, *woh, *wol;
    fp16 *Fqh, *Fql, *Gh, *Gl, *Hvh, *Hvl, *Rh, *Rl;
    float *S, *stM, *stS, *rowM, *rowIL;
    cudaGetSymbolAddress((void**)&FcTh, g_FcT_h); cudaGetSymbolAddress((void**)&FcTl, g_FcT_l);
    cudaGetSymbolAddress((void**)&FsTh, g_FsT_h); cudaGetSymbolAddress((void**)&FsTl, g_FsT_l);
    cudaGetSymbolAddress((void**)&wfh, g_wf_h);   cudaGetSymbolAddress((void**)&wfl, g_wf_l);
    cudaGetSymbolAddress((void**)&wgh, g_wg_h);   cudaGetSymbolAddress((void**)&wgl, g_wg_l);
    cudaGetSymbolAddress((void**)&whh, g_wh_h);   cudaGetSymbolAddress((void**)&whl, g_wh_l);
    cudaGetSymbolAddress((void**)&woh, g_wo_h);   cudaGetSymbolAddress((void**)&wol, g_wo_l);
    cudaGetSymbolAddress((void**)&Fqh, g_Fq_h);   cudaGetSymbolAddress((void**)&Fql, g_Fq_l);
    cudaGetSymbolAddress((void**)&Gh,  g_G_h);    cudaGetSymbolAddress((void**)&Gl,  g_G_l);
    cudaGetSymbolAddress((void**)&Hvh, g_Hv_h);   cudaGetSymbolAddress((void**)&Hvl, g_Hv_l);
    cudaGetSymbolAddress((void**)&Rh,  g_R_h);    cudaGetSymbolAddress((void**)&Rl,  g_R_l);
    cudaGetSymbolAddress((void**)&S,   g_S);
    cudaGetSymbolAddress((void**)&stM, g_stM);    cudaGetSymbolAddress((void**)&stS, g_stS);
    cudaGetSymbolAddress((void**)&rowM, g_rowM);  cudaGetSymbolAddress((void**)&rowIL, g_rowIL);

    cudaFuncSetAttribute((const void*)mma_gemm<2,false,false,3>, cudaFuncAttributeMaxDynamicSharedMemorySize, DSMEM);
    cudaFuncSetAttribute((const void*)mma_gemm<1,false,false,2>, cudaFuncAttributeMaxDynamicSharedMemorySize, DSMEM);
    cudaFuncSetAttribute((const void*)mma_gemm<0,true ,false,3>, cudaFuncAttributeMaxDynamicSharedMemorySize, DSMEM);
    cudaFuncSetAttribute((const void*)mma_gemm<2,false,true ,1>, cudaFuncAttributeMaxDynamicSharedMemorySize, DSMEM_F);
    cudaFuncSetAttribute((const void*)mma_gemm<0,false,false,2>, cudaFuncAttributeMaxDynamicSharedMemorySize, DSMEM);

    const long long cn = (long long)NPIX * CDIM;
    const long long nn = (long long)NPIX * NPIX;

    dim3 gConv(NPIX / 128, CDIM / 128, BATCH);   // 32 x 2 x 4
    dim3 gS(NPIX / 128, NPIX / 128, BATCH);      // 32 x 32 x 4

    wsplit_all<<<dim3(256, 4), 256>>>(w_f, w_g, w_h, w_o,
        wfh, wfl, wgh, wgl, whh, whl, woh, wol);
    tsplit_both<<<dim3(128, 8, 8), dim3(32, 8)>>>(F_c, F_s, FcTh, FcTl, FsTh, FsTl);
    // G1: Fq_t (3-pass, feeds softmax)
    mma_gemm<2,false,false,3><<<gConv, 256, DSMEM>>>(wfh, wfl, FcTh, FcTl,
        CDIM, CDIM, CDIM, CDIM, 0, cn, cn, b_f, nullptr, Fqh, Fql,
        nullptr, nullptr, nullptr, nullptr, nullptr);
    // G2: G_t (3-pass)
    mma_gemm<2,false,false,3><<<gConv, 256, DSMEM>>>(wgh, wgl, FsTh, FsTl,
        CDIM, CDIM, CDIM, CDIM, 0, cn, cn, b_g, nullptr, Gh, Gl,
        nullptr, nullptr, nullptr, nullptr, nullptr);
    // G4: S logits (3-pass) + stats — ncu target
    mma_gemm<0,true,false,3><<<gS, 256, DSMEM>>>(Fqh, Fql, Gh, Gl,
        CDIM, CDIM, CDIM, NPIX, cn, cn, nn, nullptr, S, nullptr, nullptr,
        nullptr, nullptr, nullptr, stM, stS);
    // G3: Hv (2-pass: w_h split, F_s rounded = FsTh)
    mma_gemm<1,false,false,2><<<gConv, 256, DSMEM>>>(whh, whl, FsTh, nullptr,
        CDIM, CDIM, CDIM, NPIX, 0, cn, cn, b_h, nullptr, Hvh, Hvl,
        nullptr, nullptr, nullptr, nullptr, nullptr);
    // stats fold
    combine_stats<<<(BATCH * NPIX + 255) / 256, 256>>>(stM, stS, rowM, rowIL);
    // G5: R_t (1-pass: Hvh x P rounded, P fused from fp32 S)
    mma_gemm<2,false,true,1><<<gConv, 256, DSMEM_F>>>(Hvh, nullptr, nullptr, nullptr,
        NPIX, NPIX, NPIX, CDIM, cn, nn, cn, nullptr, nullptr, Rh, Rl,
        S, rowM, rowIL, nullptr, nullptr);
    // G6: out (2-pass: w_o split, R rounded = Rh)
    mma_gemm<0,false,false,2><<<gConv, 256, DSMEM>>>(woh, wol, Rh, nullptr,
        CDIM, CDIM, CDIM, NPIX, 0, cn, cn, b_o, out, nullptr, nullptr,
        nullptr, nullptr, nullptr, nullptr, nullptr);
}

// round 9
// speedup vs baseline: 1.2716x; 1.0304x over previous
#include <cuda_runtime.h>
#include <cuda_fp16.h>
#include <cstdint>

#define BATCH 4
#define CDIM  256
#define NPIX  4096
typedef __half fp16;

#define CN ((size_t)BATCH * NPIX * CDIM)      // 4,194,304
#define NN ((size_t)BATCH * NPIX * NPIX)      // 67,108,864

// ---------------------------------------------------------------------------
// Device scratch
// ---------------------------------------------------------------------------
__device__ fp16  g_FcT_h[CN], g_FcT_l[CN];    // F_c transposed [b][p][c]
__device__ fp16  g_FsT_h[CN], g_FsT_l[CN];
__device__ fp16  g_wf_h[CDIM*CDIM], g_wf_l[CDIM*CDIM];
__device__ fp16  g_wg_h[CDIM*CDIM], g_wg_l[CDIM*CDIM];
__device__ fp16  g_wh_h[CDIM*CDIM], g_wh_l[CDIM*CDIM];
__device__ fp16  g_wo_h[CDIM*CDIM], g_wo_l[CDIM*CDIM];
__device__ fp16  g_Fq_h[CN], g_Fq_l[CN];      // [b][i][c]
__device__ fp16  g_G_h [CN], g_G_l [CN];      // [b][j][c]
__device__ fp16  g_Hv_h[CN];                  // [b][c][j]
__device__ fp16  g_R_h [CN];                  // [b][i][c]
__device__ fp16  g_E[NN];                     // E = exp(S - m_tile), fp16
__device__ float g_stM[(size_t)BATCH * 32 * NPIX];
__device__ float g_stS[(size_t)BATCH * 32 * NPIX];
__device__ float g_rowM[(size_t)BATCH * NPIX];
__device__ float g_rowIL[(size_t)BATCH * NPIX];

// ---------------------------------------------------------------------------
// PTX helpers (sm_80-level only)
// ---------------------------------------------------------------------------
__device__ __forceinline__ uint32_t smem_u32(const void* p) {
    uint32_t a;
    asm("{ .reg .u64 t; cvta.to.shared.u64 t, %1; cvt.u32.u64 %0, t; }" : "=r"(a) : "l"(p));
    return a;
}
#define CPA(s, g) asm volatile("cp.async.cg.shared.global [%0], [%1], 16;" :: "r"(s), "l"(g) : "memory")
#define CPC()     asm volatile("cp.async.commit_group;" ::: "memory")
#define CPW(n)    asm volatile("cp.async.wait_group %0;" :: "n"(n) : "memory")

__device__ __forceinline__ void ldsm4(uint32_t* r, uint32_t a) {
    asm volatile("ldmatrix.sync.aligned.m8n8.x4.shared.b16 {%0,%1,%2,%3}, [%4];"
        : "=r"(r[0]), "=r"(r[1]), "=r"(r[2]), "=r"(r[3]) : "r"(a));
}
__device__ __forceinline__ void ldsm2(uint32_t* r, uint32_t a) {
    asm volatile("ldmatrix.sync.aligned.m8n8.x2.shared.b16 {%0,%1}, [%2];"
        : "=r"(r[0]), "=r"(r[1]) : "r"(a));
}
__device__ __forceinline__ void mma_fp16(float* c, const uint32_t* a, const uint32_t* b) {
    asm volatile("mma.sync.aligned.m16n8k16.row.col.f32.f16.f16.f32 "
        "{%0,%1,%2,%3}, {%4,%5,%6,%7}, {%8,%9}, {%0,%1,%2,%3};"
        : "+f"(c[0]), "+f"(c[1]), "+f"(c[2]), "+f"(c[3])
        : "r"(a[0]), "r"(a[1]), "r"(a[2]), "r"(a[3]), "r"(b[0]), "r"(b[1]));
}
__device__ __forceinline__ void split2h(float x, fp16& h, fp16& l) {
    h = __float2half_rn(x);
    l = __float2half_rn(x - __half2float(h));
}

// ---------------------------------------------------------------------------
// GEMM: D[m,n] = sum_k A[m,k]*B[n,k]; K-contiguous fp16 hi/lo operands.
// CTA 128x128, BK=32, 8 warps (warp tile 64x32).
// PIPE=3: 3-stage cp.async, SINGLE sync per chunk, full fragment preload,
//         1 CTA/SM (regs ~190, smem 120KB).
// PIPE=2: R8 2-stage loop (used for FUSEB), 2 CTAs/SM.
// PASSES: 3 = Ah·Bh + Al·Bh + Ah·Bl ; 2 = Ah·Bh + Al·Bh ; 1 = Ah·Bh
// EPI:    0 fp32 [m][n](+bias); 1 fp16 split [m][n] (lo optional);
//         2 fp16 split transposed [n][m] (lo optional);
//         3 E=exp(D - rowtile max) fp16 [m][n] + stats (G4)
// FUSEB:  B tile built in-kernel: fp16 E staged via cp.async, scaled by
//         exp(m_tile - m)*il (G5)
// ---------------------------------------------------------------------------
#define RSB      80
#define TILE_SB  (128 * RSB)     // 10240
#define STAGE_SB (4 * TILE_SB)   // 40960
#define SF_SB    (128 * 80)      // 10240 (fp16 E staging, 64B rows + pad)
#define DSMEM3   (3 * STAGE_SB)            // 122880
#define DSMEM_F  (2 * STAGE_SB + SF_SB)    // 92160

template <int EPI, bool FUSEB, int PASSES, int PIPE, int MINCTA>
__global__ void __launch_bounds__(256, MINCTA)
mma_gemm(const fp16* __restrict__ Ah_, const fp16* __restrict__ Al_,
         const fp16* __restrict__ Bh_, const fp16* __restrict__ Bl_,
         int K, int lda, int ldb, int ldo,
         long long sA, long long sB, long long sO,
         const float* __restrict__ bias,
         float* __restrict__ outF, fp16* __restrict__ oH, fp16* __restrict__ oL,
         const fp16* __restrict__ Efp, const float* __restrict__ rowM,
         const float* __restrict__ rowIL,
         float* __restrict__ stM, float* __restrict__ stS)
{
    extern __shared__ char smem[];
    const uint32_t sb = smem_u32(smem);
    const int tid = threadIdx.x;
    const int lane = tid & 31, wid = tid >> 5;
    const int wm = wid >> 2, wn = wid & 3;        // 2 x 4 warp grid
    const int z = blockIdx.z;
    const int m0 = blockIdx.y * 128, n0 = blockIdx.x * 128;

    const fp16* pT[4] = {Ah_ + (size_t)z * sA,
                         (PASSES >= 2) ? Al_ + (size_t)z * sA : nullptr,
                         FUSEB ? nullptr : Bh_ + (size_t)z * sB,
                         (!FUSEB && PASSES >= 3) ? Bl_ + (size_t)z * sB : nullptr};
    const int nk = K / 32;

    const int r0 = tid >> 2, c0 = tid & 3;
    const int r1 = r0 + 64;

    auto issueA = [&](int kc) {
        if (kc >= nk) return;
        const uint32_t s0 = sb + (uint32_t)(PIPE == 3 ? (kc % 3) : (kc & 1)) * STAGE_SB;
#pragma unroll
        for (int t = 0; t < 4; ++t) {
            if (t == 1 && PASSES < 2) continue;
            if (t >= 2 && FUSEB) continue;
            if (t == 3 && PASSES < 3) continue;
            const int ld = (t < 2) ? lda : ldb;
            const int base = (t < 2) ? m0 : n0;
            const fp16* g0 = pT[t] + (size_t)(base + r0) * ld + kc * 32 + c0 * 8;
            const fp16* g1 = pT[t] + (size_t)(base + r1) * ld + kc * 32 + c0 * 8;
            CPA(s0 + t * TILE_SB + r0 * RSB + c0 * 16, g0);
            CPA(s0 + t * TILE_SB + r1 * RSB + c0 * 16, g1);
        }
    };

    // FUSEB: per-thread row of the E tile
    const int pr = tid >> 1, jh = tid & 1;
    const uint32_t sf = sb + 2 * STAGE_SB;
    float mrow = 0.f, il = 0.f;
    const fp16* Erow = nullptr;
    if (FUSEB) {
        Erow = Efp + (size_t)z * sB + (size_t)(n0 + pr) * ldb;
        mrow = rowM [(size_t)z * NPIX + n0 + pr];
        il   = rowIL[(size_t)z * NPIX + n0 + pr];
    }
    auto issueS = [&](int kc) {
        if (kc >= nk) return;
        const uint32_t d = sf + pr * 80 + jh * 32;
        const fp16* g = Erow + kc * 32 + jh * 16;
        CPA(d, g); CPA(d + 16, g + 8);
    };
    auto convB = [&](int kc) {   // E fp16 -> P = E * exp(mt - m) * il -> fp16 tile
        const uint32_t s0 = sb + (kc & 1) * STAGE_SB;
        const int tile = kc >> 2;
        const float st = stM[((size_t)z * 32 + tile) * NPIX + (n0 + pr)];
        const float scale = __expf(st - mrow) * il;
        const __half2* Ef = (const __half2*)(smem + 2 * STAGE_SB + pr * 80 + jh * 32);
        const uint32_t dH = s0 + 2 * TILE_SB + pr * RSB + jh * 32;
        uint32_t w[8];
#pragma unroll
        for (int q = 0; q < 8; ++q) {
            float2 e = __half22float2(Ef[q]);
            __half2 hp = __floats2half2_rn(e.x * scale, e.y * scale);
            w[q] = *(uint32_t*)&hp;
        }
        asm volatile("st.shared.v4.b32 [%0], {%1,%2,%3,%4};"
            :: "r"(dH), "r"(w[0]), "r"(w[1]), "r"(w[2]), "r"(w[3]) : "memory");
        asm volatile("st.shared.v4.b32 [%0], {%1,%2,%3,%4};"
            :: "r"(dH + 16), "r"(w[4]), "r"(w[5]), "r"(w[6]), "r"(w[7]) : "memory");
    };

    float acc[4][4][4];
#pragma unroll
    for (int i = 0; i < 4; ++i)
#pragma unroll
        for (int j = 0; j < 4; ++j)
#pragma unroll
            for (int q = 0; q < 4; ++q) acc[i][j][q] = 0.f;

    issueA(0); if (FUSEB) issueS(0); CPC();
    issueA(1); CPC();

    const int aRow = lane & 15;
    const int aKB  = (lane >> 4) * 16;
    const int bRow = lane & 7;
    const int bKB  = ((lane >> 3) & 1) * 16;

    if (PIPE == 3) {
        // ---- 3-stage, single sync per chunk, full fragment preload ----
        for (int kc = 0; kc < nk; ++kc) {
            CPW(1);
            __syncthreads();
            issueA(kc + 2); CPC();
            const uint32_t s0 = sb + (uint32_t)(kc % 3) * STAGE_SB;
            const uint32_t aH = s0, aL = s0 + TILE_SB;
            const uint32_t bH = s0 + 2 * TILE_SB, bL = s0 + 3 * TILE_SB;
            uint32_t Af[2][2][4][4];
            uint32_t Bf[2][2][4][2];
#pragma unroll
            for (int ks = 0; ks < 2; ++ks) {
#pragma unroll
                for (int i = 0; i < 4; ++i) {
                    const uint32_t off = (uint32_t)(wm * 64 + i * 16 + aRow) * RSB + ks * 32 + aKB;
                    ldsm4(Af[ks][0][i], aH + off);
                    if (PASSES >= 2) ldsm4(Af[ks][1][i], aL + off);
                }
#pragma unroll
                for (int j = 0; j < 4; ++j) {
                    const uint32_t off = (uint32_t)(wn * 32 + j * 8 + bRow) * RSB + ks * 32 + bKB;
                    ldsm2(Bf[ks][0][j], bH + off);
                    if (PASSES >= 3) ldsm2(Bf[ks][1][j], bL + off);
                }
            }
#pragma unroll
            for (int ks = 0; ks < 2; ++ks) {
#pragma unroll
                for (int j = 0; j < 4; ++j)
#pragma unroll
                    for (int i = 0; i < 4; ++i)
                        mma_fp16(acc[i][j], Af[ks][0][i], Bf[ks][0][j]);
                if (PASSES >= 2)
#pragma unroll
                    for (int j = 0; j < 4; ++j)
#pragma unroll
                        for (int i = 0; i < 4; ++i)
                            mma_fp16(acc[i][j], Af[ks][1][i], Bf[ks][0][j]);
                if (PASSES >= 3)
#pragma unroll
                    for (int j = 0; j < 4; ++j)
#pragma unroll
                        for (int i = 0; i < 4; ++i)
                            mma_fp16(acc[i][j], Af[ks][0][i], Bf[ks][1][j]);
            }
        }
        __syncthreads();   // protect stg overwrite of stage smem
    } else {
        // ---- R8 2-stage loop (FUSEB path) ----
        for (int kc = 0; kc < nk; ++kc) {
            CPW(1);
            if (FUSEB) convB(kc);
            __syncthreads();
            const uint32_t s0 = sb + (kc & 1) * STAGE_SB;
            const uint32_t aH = s0, aL = s0 + TILE_SB;
            const uint32_t bH = s0 + 2 * TILE_SB, bL = s0 + 3 * TILE_SB;
#pragma unroll
            for (int ks = 0; ks < 2; ++ks) {
                uint32_t Af[2][4][4];
#pragma unroll
                for (int i = 0; i < 4; ++i) {
                    const uint32_t off = (uint32_t)(wm * 64 + i * 16 + aRow) * RSB + ks * 32 + aKB;
                    ldsm4(Af[0][i], aH + off);
                    if (PASSES >= 2) ldsm4(Af[1][i], aL + off);
                }
#pragma unroll
                for (int jp = 0; jp < 2; ++jp) {
                    uint32_t Bf[2][2][2];
#pragma unroll
                    for (int jj = 0; jj < 2; ++jj) {
                        const int j = jp * 2 + jj;
                        const uint32_t off = (uint32_t)(wn * 32 + j * 8 + bRow) * RSB + ks * 32 + bKB;
                        ldsm2(Bf[0][jj], bH + off);
                        if (PASSES >= 3) ldsm2(Bf[1][jj], bL + off);
                    }
#pragma unroll
                    for (int jj = 0; jj < 2; ++jj)
#pragma unroll
                        for (int i = 0; i < 4; ++i)
                            mma_fp16(acc[i][jp * 2 + jj], Af[0][i], Bf[0][jj]);
                    if (PASSES >= 2)
#pragma unroll
                        for (int jj = 0; jj < 2; ++jj)
#pragma unroll
                            for (int i = 0; i < 4; ++i)
                                mma_fp16(acc[i][jp * 2 + jj], Af[1][i], Bf[0][jj]);
                    if (PASSES >= 3)
#pragma unroll
                        for (int jj = 0; jj < 2; ++jj)
#pragma unroll
                            for (int i = 0; i < 4; ++i)
                                mma_fp16(acc[i][jp * 2 + jj], Af[0][i], Bf[1][jj]);
                }
            }
            __syncthreads();
            if (FUSEB) { issueS(kc + 1); CPC(); issueA(kc + 2); CPC(); }
            else       { issueA(kc + 2); CPC(); }
        }
    }

    // ---- epilogue: stage D (+bias on m) through smem ----
    float* stg = (float*)smem;                   // [128][132]
    const int gid = lane >> 2, tig = lane & 3;
#pragma unroll
    for (int i = 0; i < 4; ++i) {
        const int ml = wm * 64 + i * 16 + gid;
        const float bv0 = bias ? bias[m0 + ml] : 0.f;
        const float bv8 = bias ? bias[m0 + ml + 8] : 0.f;
#pragma unroll
        for (int j = 0; j < 4; ++j) {
            const int nl = wn * 32 + j * 8 + tig * 2;
            stg[ml * 132 + nl]           = acc[i][j][0] + bv0;
            stg[ml * 132 + nl + 1]       = acc[i][j][1] + bv0;
            stg[(ml + 8) * 132 + nl]     = acc[i][j][2] + bv8;
            stg[(ml + 8) * 132 + nl + 1] = acc[i][j][3] + bv8;
        }
    }
    __syncthreads();

    const int row = tid >> 1, half = tid & 1;
    if (EPI == 0) {
        float* dst = outF + (size_t)z * sO + (size_t)(m0 + row) * ldo + n0 + half * 64;
        const float4* s4 = (const float4*)&stg[row * 132 + half * 64];
#pragma unroll
        for (int i = 0; i < 16; ++i) ((float4*)dst)[i] = s4[i];
    } else if (EPI == 1) {
        const size_t base = (size_t)z * sO + (size_t)(m0 + row) * ldo + n0 + half * 64;
#pragma unroll
        for (int v = 0; v < 8; ++v) {
            uint32_t hw[4], lw[4];
#pragma unroll
            for (int q = 0; q < 4; ++q) {
                float x0 = stg[row * 132 + half * 64 + v * 8 + q * 2];
                float x1 = stg[row * 132 + half * 64 + v * 8 + q * 2 + 1];
                fp16 h0, l0, h1, l1;
                split2h(x0, h0, l0); split2h(x1, h1, l1);
                __half2 hp = __halves2half2(h0, h1), lp = __halves2half2(l0, l1);
                hw[q] = *(uint32_t*)&hp; lw[q] = *(uint32_t*)&lp;
            }
            *(uint4*)(oH + base + v * 8) = make_uint4(hw[0], hw[1], hw[2], hw[3]);
            if (oL) *(uint4*)(oL + base + v * 8) = make_uint4(lw[0], lw[1], lw[2], lw[3]);
        }
    } else if (EPI == 2) {
        const int n = row, mh = half * 64;
        const size_t base = (size_t)z * sO + (size_t)(n0 + n) * ldo + m0 + mh;
#pragma unroll
        for (int v = 0; v < 8; ++v) {
            uint32_t hw[4], lw[4];
#pragma unroll
            for (int q = 0; q < 4; ++q) {
                float x0 = stg[(mh + v * 8 + q * 2) * 132 + n];
                float x1 = stg[(mh + v * 8 + q * 2 + 1) * 132 + n];
                fp16 h0, l0, h1, l1;
                split2h(x0, h0, l0); split2h(x1, h1, l1);
                __half2 hp = __halves2half2(h0, h1), lp = __halves2half2(l0, l1);
                hw[q] = *(uint32_t*)&hp; lw[q] = *(uint32_t*)&lp;
            }
            *(uint4*)(oH + base + v * 8) = make_uint4(hw[0], hw[1], hw[2], hw[3]);
            if (oL) *(uint4*)(oL + base + v * 8) = make_uint4(lw[0], lw[1], lw[2], lw[3]);
        }
    } else {   // EPI == 3: E = exp(D - tile max) fp16 + stats
        const size_t base = (size_t)z * sO + (size_t)(m0 + row) * ldo + n0 + half * 64;
        const float* src = &stg[row * 132 + half * 64];
        float mx = -3.0e38f;
#pragma unroll
        for (int q = 0; q < 64; ++q) mx = fmaxf(mx, src[q]);
        mx = fmaxf(mx, __shfl_xor_sync(0xffffffffu, mx, 1));
        float s = 0.f;
#pragma unroll
        for (int v = 0; v < 8; ++v) {
            uint32_t w[4];
#pragma unroll
            for (int q = 0; q < 4; ++q) {
                float e0 = __expf(src[v * 8 + q * 2]     - mx);
                float e1 = __expf(src[v * 8 + q * 2 + 1] - mx);
                s += e0 + e1;
                __half2 hp = __floats2half2_rn(e0, e1);
                w[q] = *(uint32_t*)&hp;
            }
            *(uint4*)(oH + base + v * 8) = make_uint4(w[0], w[1], w[2], w[3]);
        }
        s += __shfl_xor_sync(0xffffffffu, s, 1);
        if (half == 0) {
            size_t o = ((size_t)z * 32 + blockIdx.x) * NPIX + m0 + row;
            stM[o] = mx; stS[o] = s;
        }
    }
}

// ---------------------------------------------------------------------------
__global__ void __launch_bounds__(256)
combine_stats(const float* __restrict__ stM, const float* __restrict__ stS,
              float* __restrict__ rowM, float* __restrict__ rowIL)
{
    const int idx = blockIdx.x * 256 + threadIdx.x;
    if (idx >= BATCH * NPIX) return;
    const int z = idx >> 12, i = idx & (NPIX - 1);
    float m = -3.0e38f;
#pragma unroll 4
    for (int t = 0; t < 32; ++t)
        m = fmaxf(m, stM[((size_t)z * 32 + t) * NPIX + i]);
    float l = 0.f;
#pragma unroll 4
    for (int t = 0; t < 32; ++t) {
        size_t o = ((size_t)z * 32 + t) * NPIX + i;
        l += stS[o] * __expf(stM[o] - m);
    }
    rowM[idx] = m;
    rowIL[idx] = 1.0f / l;
}

// ---------------------------------------------------------------------------
__global__ void __launch_bounds__(256)
tsplit_both(const float* __restrict__ Fc, const float* __restrict__ Fs,
            fp16* __restrict__ ohc, fp16* __restrict__ olc,
            fp16* __restrict__ ohs, fp16* __restrict__ ols)
{
    __shared__ float t[32][33];
    const int zz = blockIdx.z;
    const int b = zz & 3;
    const float* X = (zz < 4) ? Fc : Fs;
    fp16* oh = (zz < 4) ? ohc : ohs;
    fp16* ol = (zz < 4) ? olc : ols;
    const int pb = blockIdx.x * 32, cb = blockIdx.y * 32;
    const float* src = X + (size_t)b * CDIM * NPIX;
#pragma unroll
    for (int j = 0; j < 4; ++j) {
        int c = cb + threadIdx.y + j * 8;
        t[threadIdx.y + j * 8][threadIdx.x] = src[(size_t)c * NPIX + pb + threadIdx.x];
    }
    __syncthreads();
#pragma unroll
    for (int j = 0; j < 4; ++j) {
        int p = pb + threadIdx.y + j * 8;
        float v = t[threadIdx.x][threadIdx.y + j * 8];
        size_t o = (size_t)b * NPIX * CDIM + (size_t)p * CDIM + cb + threadIdx.x;
        fp16 h, l; split2h(v, h, l);
        oh[o] = h; ol[o] = l;
    }
}

__global__ void __launch_bounds__(256)
wsplit_all(const float* __restrict__ w0, const float* __restrict__ w1,
           const float* __restrict__ w2, const float* __restrict__ w3,
           fp16* __restrict__ h0, fp16* __restrict__ l0,
           fp16* __restrict__ h1, fp16* __restrict__ l1,
           fp16* __restrict__ h2, fp16* __restrict__ l2,
           fp16* __restrict__ h3, fp16* __restrict__ l3)
{
    const float* w = (blockIdx.y == 0) ? w0 : (blockIdx.y == 1) ? w1 : (blockIdx.y == 2) ? w2 : w3;
    fp16* hh = (blockIdx.y == 0) ? h0 : (blockIdx.y == 1) ? h1 : (blockIdx.y == 2) ? h2 : h3;
    fp16* ll = (blockIdx.y == 0) ? l0 : (blockIdx.y == 1) ? l1 : (blockIdx.y == 2) ? l2 : l3;
    int i = blockIdx.x * 256 + threadIdx.x;
    if (i < CDIM * CDIM) { fp16 a, b; split2h(w[i], a, b); hh[i] = a; ll[i] = b; }
}

// ---------------------------------------------------------------------------
extern "C" void kernel_launch(void* const* d_in, const int* in_sizes, int n_in,
                              void* d_out, int out_size)
{
    const float* F_c = (const float*)d_in[0];
    const float* F_s = (const float*)d_in[1];
    const float* w_f = (const float*)d_in[2];
    const float* b_f = (const float*)d_in[3];
    const float* w_g = (const float*)d_in[4];
    const float* b_g = (const float*)d_in[5];
    const float* w_h = (const float*)d_in[6];
    const float* b_h = (const float*)d_in[7];
    const float* w_o = (const float*)d_in[8];
    const float* b_o = (const float*)d_in[9];
    float* out = (float*)d_out;

    fp16 *FcTh, *FcTl, *FsTh, *FsTl, *wfh, *wfl, *wgh, *wgl, *whh, *whl, *woh, *wol;
    fp16 *Fqh, *Fql, *Gh, *Gl, *Hvh, *Rh, *E;
    float *stM, *stS, *rowM, *rowIL;
    cudaGetSymbolAddress((void**)&FcTh, g_FcT_h); cudaGetSymbolAddress((void**)&FcTl, g_FcT_l);
    cudaGetSymbolAddress((void**)&FsTh, g_FsT_h); cudaGetSymbolAddress((void**)&FsTl, g_FsT_l);
    cudaGetSymbolAddress((void**)&wfh, g_wf_h);   cudaGetSymbolAddress((void**)&wfl, g_wf_l);
    cudaGetSymbolAddress((void**)&wgh, g_wg_h);   cudaGetSymbolAddress((void**)&wgl, g_wg_l);
    cudaGetSymbolAddress((void**)&whh, g_wh_h);   cudaGetSymbolAddress((void**)&whl, g_wh_l);
    cudaGetSymbolAddress((void**)&woh, g_wo_h);   cudaGetSymbolAddress((void**)&wol, g_wo_l);
    cudaGetSymbolAddress((void**)&Fqh, g_Fq_h);   cudaGetSymbolAddress((void**)&Fql, g_Fq_l);
    cudaGetSymbolAddress((void**)&Gh,  g_G_h);    cudaGetSymbolAddress((void**)&Gl,  g_G_l);
    cudaGetSymbolAddress((void**)&Hvh, g_Hv_h);   cudaGetSymbolAddress((void**)&Rh,  g_R_h);
    cudaGetSymbolAddress((void**)&E,   g_E);
    cudaGetSymbolAddress((void**)&stM, g_stM);    cudaGetSymbolAddress((void**)&stS, g_stS);
    cudaGetSymbolAddress((void**)&rowM, g_rowM);  cudaGetSymbolAddress((void**)&rowIL, g_rowIL);

    cudaFuncSetAttribute((const void*)mma_gemm<2,false,3,3,1>, cudaFuncAttributeMaxDynamicSharedMemorySize, DSMEM3);
    cudaFuncSetAttribute((const void*)mma_gemm<3,false,3,3,1>, cudaFuncAttributeMaxDynamicSharedMemorySize, DSMEM3);
    cudaFuncSetAttribute((const void*)mma_gemm<1,false,2,3,1>, cudaFuncAttributeMaxDynamicSharedMemorySize, DSMEM3);
    cudaFuncSetAttribute((const void*)mma_gemm<0,false,2,3,1>, cudaFuncAttributeMaxDynamicSharedMemorySize, DSMEM3);
    cudaFuncSetAttribute((const void*)mma_gemm<2,true ,1,2,2>, cudaFuncAttributeMaxDynamicSharedMemorySize, DSMEM_F);

    const long long cn = (long long)NPIX * CDIM;
    const long long nn = (long long)NPIX * NPIX;

    dim3 gConv(NPIX / 128, CDIM / 128, BATCH);   // 32 x 2 x 4
    dim3 gS(NPIX / 128, NPIX / 128, BATCH);      // 32 x 32 x 4

    // L1, L2: conversions
    wsplit_all<<<dim3(256, 4), 256>>>(w_f, w_g, w_h, w_o,
        wfh, wfl, wgh, wgl, whh, whl, woh, wol);
    tsplit_both<<<dim3(128, 8, 8), dim3(32, 8)>>>(F_c, F_s, FcTh, FcTl, FsTh, FsTl);
    // L3 (G1): Fq_t (3-pass, PIPE3)
    mma_gemm<2,false,3,3,1><<<gConv, 256, DSMEM3>>>(wfh, wfl, FcTh, FcTl,
        CDIM, CDIM, CDIM, CDIM, 0, cn, cn, b_f, nullptr, Fqh, Fql,
        nullptr, nullptr, nullptr, nullptr, nullptr);
    // L4 (G2): G_t (3-pass, PIPE3)
    mma_gemm<2,false,3,3,1><<<gConv, 256, DSMEM3>>>(wgh, wgl, FsTh, FsTl,
        CDIM, CDIM, CDIM, CDIM, 0, cn, cn, b_g, nullptr, Gh, Gl,
        nullptr, nullptr, nullptr, nullptr, nullptr);
    // L5 (G4): E = exp(S - m_tile) fp16 + stats (3-pass, PIPE3) — ncu target
    mma_gemm<3,false,3,3,1><<<gS, 256, DSMEM3>>>(Fqh, Fql, Gh, Gl,
        CDIM, CDIM, CDIM, NPIX, cn, cn, nn, nullptr, nullptr, E, nullptr,
        nullptr, nullptr, nullptr, stM, stS);
    // L6 (G3): Hv hi only (2-pass, PIPE3)
    mma_gemm<1,false,2,3,1><<<gConv, 256, DSMEM3>>>(whh, whl, FsTh, nullptr,
        CDIM, CDIM, CDIM, NPIX, 0, cn, cn, b_h, nullptr, Hvh, nullptr,
        nullptr, nullptr, nullptr, nullptr, nullptr);
    // L7: stats fold
    combine_stats<<<(BATCH * NPIX + 255) / 256, 256>>>(stM, stS, rowM, rowIL);
    // L8 (G5): R_t hi only (1-pass, FUSEB from fp16 E, PIPE2)
    mma_gemm<2,true,1,2,2><<<gConv, 256, DSMEM_F>>>(Hvh, nullptr, nullptr, nullptr,
        NPIX, NPIX, NPIX, CDIM, cn, nn, cn, nullptr, nullptr, Rh, nullptr,
        E, rowM, rowIL, stM, nullptr);
    // L9 (G6): out = w_o @ R + b_o (2-pass, PIPE3)
    mma_gemm<0,false,2,3,1><<<gConv, 256, DSMEM3>>>(woh, wol, Rh, nullptr,
        CDIM, CDIM, CDIM, NPIX, 0, cn, cn, b_o, out, nullptr, nullptr,
        nullptr, nullptr, nullptr, nullptr, nullptr);
}

// round 10
// speedup vs baseline: 1.2772x; 1.0044x over previous
#include <cuda_runtime.h>
#include <cuda_fp16.h>
#include <cstdint>

#define BATCH 4
#define CDIM  256
#define NPIX  4096
typedef __half fp16;

#define CN ((size_t)BATCH * NPIX * CDIM)      // 4,194,304
#define NN ((size_t)BATCH * NPIX * NPIX)      // 67,108,864

// ---------------------------------------------------------------------------
// Device scratch
// ---------------------------------------------------------------------------
__device__ fp16  g_FcT_h[CN], g_FcT_l[CN];    // F_c transposed [b][p][c]
__device__ fp16  g_FsT_h[CN], g_FsT_l[CN];
__device__ fp16  g_wf_h[CDIM*CDIM], g_wf_l[CDIM*CDIM];
__device__ fp16  g_wg_h[CDIM*CDIM], g_wg_l[CDIM*CDIM];
__device__ fp16  g_wh_h[CDIM*CDIM], g_wh_l[CDIM*CDIM];
__device__ fp16  g_wo_h[CDIM*CDIM], g_wo_l[CDIM*CDIM];
__device__ fp16  g_Fq_h[CN], g_Fq_l[CN];      // [b][i][c]
__device__ fp16  g_G_h [CN], g_G_l [CN];      // [b][j][c]
__device__ fp16  g_Hv_h[CN];                  // [b][c][j]
__device__ fp16  g_R_h [CN];                  // [b][i][c]
__device__ fp16  g_E[NN];                     // E = exp(S - m_tile), fp16
__device__ float g_stM[(size_t)BATCH * 32 * NPIX];
__device__ float g_stS[(size_t)BATCH * 32 * NPIX];
__device__ float g_rowM[(size_t)BATCH * NPIX];
__device__ float g_rowIL[(size_t)BATCH * NPIX];

// ---------------------------------------------------------------------------
// PTX helpers (sm_80-level only)
// ---------------------------------------------------------------------------
__device__ __forceinline__ uint32_t smem_u32(const void* p) {
    uint32_t a;
    asm("{ .reg .u64 t; cvta.to.shared.u64 t, %1; cvt.u32.u64 %0, t; }" : "=r"(a) : "l"(p));
    return a;
}
#define CPA(s, g) asm volatile("cp.async.cg.shared.global [%0], [%1], 16;" :: "r"(s), "l"(g) : "memory")
#define CPC()     asm volatile("cp.async.commit_group;" ::: "memory")
#define CPW(n)    asm volatile("cp.async.wait_group %0;" :: "n"(n) : "memory")

__device__ __forceinline__ void ldsm4(uint32_t* r, uint32_t a) {
    asm volatile("ldmatrix.sync.aligned.m8n8.x4.shared.b16 {%0,%1,%2,%3}, [%4];"
        : "=r"(r[0]), "=r"(r[1]), "=r"(r[2]), "=r"(r[3]) : "r"(a));
}
__device__ __forceinline__ void ldsm2(uint32_t* r, uint32_t a) {
    asm volatile("ldmatrix.sync.aligned.m8n8.x2.shared.b16 {%0,%1}, [%2];"
        : "=r"(r[0]), "=r"(r[1]) : "r"(a));
}
__device__ __forceinline__ void mma_fp16(float* c, const uint32_t* a, const uint32_t* b) {
    asm volatile("mma.sync.aligned.m16n8k16.row.col.f32.f16.f16.f32 "
        "{%0,%1,%2,%3}, {%4,%5,%6,%7}, {%8,%9}, {%0,%1,%2,%3};"
        : "+f"(c[0]), "+f"(c[1]), "+f"(c[2]), "+f"(c[3])
        : "r"(a[0]), "r"(a[1]), "r"(a[2]), "r"(a[3]), "r"(b[0]), "r"(b[1]));
}
// fp16 accumulator variant: D/C are 2 x b32 (4 halves), same element layout
__device__ __forceinline__ void mma_hacc(uint32_t* c, const uint32_t* a, const uint32_t* b) {
    asm volatile("mma.sync.aligned.m16n8k16.row.col.f16.f16.f16.f16 "
        "{%0,%1}, {%2,%3,%4,%5}, {%6,%7}, {%0,%1};"
        : "+r"(c[0]), "+r"(c[1])
        : "r"(a[0]), "r"(a[1]), "r"(a[2]), "r"(a[3]), "r"(b[0]), "r"(b[1]));
}
__device__ __forceinline__ void split2h(float x, fp16& h, fp16& l) {
    h = __float2half_rn(x);
    l = __float2half_rn(x - __half2float(h));
}

// ---------------------------------------------------------------------------
// GEMM: D[m,n] = sum_k A[m,k]*B[n,k]; K-contiguous fp16 hi/lo operands.
// CTA 128x128, BK=32, R8 2-stage cp.async loop, 8 warps.
// PASSES: 3 = Ah·Bh + Al·Bh + Ah·Bl ; 2 = Ah·Bh + Al·Bh ; 1 = Ah·Bh
// HACC:   correction passes accumulate in packed fp16 (merged at epilogue)
// EPI:    0 fp32 [m][n](+bias); 1 fp16 [m][n]; 2 fp16 transposed [n][m];
//         3 E=exp(D - rowtile max) fp16 [m][n] + stats (G4)
// FUSEB:  B tile built in-kernel from fp16 E scaled by exp(mt-m)*il (G5)
// ---------------------------------------------------------------------------
#define RSB      80
#define TILE_SB  (128 * RSB)     // 10240
#define STAGE_SB (4 * TILE_SB)   // 40960
#define SF_SB    (128 * 80)      // 10240 (fp16 E staging)
#define DSMEM    (2 * STAGE_SB)            // 81920
#define DSMEM_F  (2 * STAGE_SB + SF_SB)    // 92160

template <int EPI, bool FUSEB, int PASSES, bool HACC, int MINCTA>
__global__ void __launch_bounds__(256, MINCTA)
mma_gemm(const fp16* __restrict__ Ah_, const fp16* __restrict__ Al_,
         const fp16* __restrict__ Bh_, const fp16* __restrict__ Bl_,
         int K, int lda, int ldb, int ldo,
         long long sA, long long sB, long long sO,
         const float* __restrict__ bias,
         float* __restrict__ outF, fp16* __restrict__ oH, fp16* __restrict__ oL,
         const fp16* __restrict__ Efp, const float* __restrict__ rowM,
         const float* __restrict__ rowIL,
         float* __restrict__ stM, float* __restrict__ stS)
{
    extern __shared__ char smem[];
    const uint32_t sb = smem_u32(smem);
    const int tid = threadIdx.x;
    const int lane = tid & 31, wid = tid >> 5;
    const int wm = wid >> 2, wn = wid & 3;        // 2 x 4 warp grid
    const int z = blockIdx.z;
    const int m0 = blockIdx.y * 128, n0 = blockIdx.x * 128;

    const fp16* pT[4] = {Ah_ + (size_t)z * sA,
                         (PASSES >= 2) ? Al_ + (size_t)z * sA : nullptr,
                         FUSEB ? nullptr : Bh_ + (size_t)z * sB,
                         (!FUSEB && PASSES >= 3) ? Bl_ + (size_t)z * sB : nullptr};
    const int nk = K / 32;

    const int r0 = tid >> 2, c0 = tid & 3;
    const int r1 = r0 + 64;

    auto issueA = [&](int kc) {
        if (kc >= nk) return;
        const uint32_t s0 = sb + (uint32_t)(kc & 1) * STAGE_SB;
#pragma unroll
        for (int t = 0; t < 4; ++t) {
            if (t == 1 && PASSES < 2) continue;
            if (t >= 2 && FUSEB) continue;
            if (t == 3 && PASSES < 3) continue;
            const int ld = (t < 2) ? lda : ldb;
            const int base = (t < 2) ? m0 : n0;
            const fp16* g0 = pT[t] + (size_t)(base + r0) * ld + kc * 32 + c0 * 8;
            const fp16* g1 = pT[t] + (size_t)(base + r1) * ld + kc * 32 + c0 * 8;
            CPA(s0 + t * TILE_SB + r0 * RSB + c0 * 16, g0);
            CPA(s0 + t * TILE_SB + r1 * RSB + c0 * 16, g1);
        }
    };

    // FUSEB: per-thread row of the E tile
    const int pr = tid >> 1, jh = tid & 1;
    const uint32_t sf = sb + 2 * STAGE_SB;
    float mrow = 0.f, il = 0.f;
    const fp16* Erow = nullptr;
    if (FUSEB) {
        Erow = Efp + (size_t)z * sB + (size_t)(n0 + pr) * ldb;
        mrow = rowM [(size_t)z * NPIX + n0 + pr];
        il   = rowIL[(size_t)z * NPIX + n0 + pr];
    }
    auto issueS = [&](int kc) {
        if (kc >= nk) return;
        const uint32_t d = sf + pr * 80 + jh * 32;
        const fp16* g = Erow + kc * 32 + jh * 16;
        CPA(d, g); CPA(d + 16, g + 8);
    };
    auto convB = [&](int kc) {
        const uint32_t s0 = sb + (kc & 1) * STAGE_SB;
        const int tile = kc >> 2;
        const float st = stM[((size_t)z * 32 + tile) * NPIX + (n0 + pr)];
        const float scale = __expf(st - mrow) * il;
        const __half2* Ef = (const __half2*)(smem + 2 * STAGE_SB + pr * 80 + jh * 32);
        const uint32_t dH = s0 + 2 * TILE_SB + pr * RSB + jh * 32;
        uint32_t w[8];
#pragma unroll
        for (int q = 0; q < 8; ++q) {
            float2 e = __half22float2(Ef[q]);
            __half2 hp = __floats2half2_rn(e.x * scale, e.y * scale);
            w[q] = *(uint32_t*)&hp;
        }
        asm volatile("st.shared.v4.b32 [%0], {%1,%2,%3,%4};"
            :: "r"(dH), "r"(w[0]), "r"(w[1]), "r"(w[2]), "r"(w[3]) : "memory");
        asm volatile("st.shared.v4.b32 [%0], {%1,%2,%3,%4};"
            :: "r"(dH + 16), "r"(w[4]), "r"(w[5]), "r"(w[6]), "r"(w[7]) : "memory");
    };

    float acc[4][4][4];
#pragma unroll
    for (int i = 0; i < 4; ++i)
#pragma unroll
        for (int j = 0; j < 4; ++j)
#pragma unroll
            for (int q = 0; q < 4; ++q) acc[i][j][q] = 0.f;
    uint32_t corr[4][4][2];
    if (HACC) {
#pragma unroll
        for (int i = 0; i < 4; ++i)
#pragma unroll
            for (int j = 0; j < 4; ++j) { corr[i][j][0] = 0u; corr[i][j][1] = 0u; }
    }

    issueA(0); if (FUSEB) issueS(0); CPC();
    issueA(1); CPC();

    const int aRow = lane & 15;
    const int aKB  = (lane >> 4) * 16;
    const int bRow = lane & 7;
    const int bKB  = ((lane >> 3) & 1) * 16;

    for (int kc = 0; kc < nk; ++kc) {
        CPW(1);
        if (FUSEB) convB(kc);
        __syncthreads();
        const uint32_t s0 = sb + (uint32_t)(kc & 1) * STAGE_SB;
        const uint32_t aH = s0, aL = s0 + TILE_SB;
        const uint32_t bH = s0 + 2 * TILE_SB, bL = s0 + 3 * TILE_SB;
#pragma unroll
        for (int ks = 0; ks < 2; ++ks) {
            uint32_t Af[2][4][4];
#pragma unroll
            for (int i = 0; i < 4; ++i) {
                const uint32_t off = (uint32_t)(wm * 64 + i * 16 + aRow) * RSB + ks * 32 + aKB;
                ldsm4(Af[0][i], aH + off);
                if (PASSES >= 2) ldsm4(Af[1][i], aL + off);
            }
#pragma unroll
            for (int jp = 0; jp < 2; ++jp) {
                uint32_t Bf[2][2][2];
#pragma unroll
                for (int jj = 0; jj < 2; ++jj) {
                    const int j = jp * 2 + jj;
                    const uint32_t off = (uint32_t)(wn * 32 + j * 8 + bRow) * RSB + ks * 32 + bKB;
                    ldsm2(Bf[0][jj], bH + off);
                    if (PASSES >= 3) ldsm2(Bf[1][jj], bL + off);
                }
                // pass 0: main, fp32 accum
#pragma unroll
                for (int jj = 0; jj < 2; ++jj)
#pragma unroll
                    for (int i = 0; i < 4; ++i)
                        mma_fp16(acc[i][jp * 2 + jj], Af[0][i], Bf[0][jj]);
                // pass 1: Al·Bh correction
                if (PASSES >= 2) {
#pragma unroll
                    for (int jj = 0; jj < 2; ++jj)
#pragma unroll
                        for (int i = 0; i < 4; ++i) {
                            if (HACC) mma_hacc(corr[i][jp * 2 + jj], Af[1][i], Bf[0][jj]);
                            else      mma_fp16(acc[i][jp * 2 + jj], Af[1][i], Bf[0][jj]);
                        }
                }
                // pass 2: Ah·Bl correction
                if (PASSES >= 3) {
#pragma unroll
                    for (int jj = 0; jj < 2; ++jj)
#pragma unroll
                        for (int i = 0; i < 4; ++i) {
                            if (HACC) mma_hacc(corr[i][jp * 2 + jj], Af[0][i], Bf[1][jj]);
                            else      mma_fp16(acc[i][jp * 2 + jj], Af[0][i], Bf[1][jj]);
                        }
                }
            }
        }
        __syncthreads();
        if (FUSEB) { issueS(kc + 1); CPC(); issueA(kc + 2); CPC(); }
        else       { issueA(kc + 2); CPC(); }
    }

    // merge fp16 corrections into fp32 accumulators
    if (HACC) {
#pragma unroll
        for (int i = 0; i < 4; ++i)
#pragma unroll
            for (int j = 0; j < 4; ++j) {
                float2 f0 = __half22float2(*(__half2*)&corr[i][j][0]);
                float2 f1 = __half22float2(*(__half2*)&corr[i][j][1]);
                acc[i][j][0] += f0.x; acc[i][j][1] += f0.y;
                acc[i][j][2] += f1.x; acc[i][j][3] += f1.y;
            }
    }

    // ---- epilogue: stage D (+bias on m) through smem ----
    float* stg = (float*)smem;                   // [128][132]
    const int gid = lane >> 2, tig = lane & 3;
#pragma unroll
    for (int i = 0; i < 4; ++i) {
        const int ml = wm * 64 + i * 16 + gid;
        const float bv0 = bias ? bias[m0 + ml] : 0.f;
        const float bv8 = bias ? bias[m0 + ml + 8] : 0.f;
#pragma unroll
        for (int j = 0; j < 4; ++j) {
            const int nl = wn * 32 + j * 8 + tig * 2;
            stg[ml * 132 + nl]           = acc[i][j][0] + bv0;
            stg[ml * 132 + nl + 1]       = acc[i][j][1] + bv0;
            stg[(ml + 8) * 132 + nl]     = acc[i][j][2] + bv8;
            stg[(ml + 8) * 132 + nl + 1] = acc[i][j][3] + bv8;
        }
    }
    __syncthreads();

    const int row = tid >> 1, half = tid & 1;
    if (EPI == 0) {
        float* dst = outF + (size_t)z * sO + (size_t)(m0 + row) * ldo + n0 + half * 64;
        const float4* s4 = (const float4*)&stg[row * 132 + half * 64];
#pragma unroll
        for (int i = 0; i < 16; ++i) ((float4*)dst)[i] = s4[i];
    } else if (EPI == 1) {
        const size_t base = (size_t)z * sO + (size_t)(m0 + row) * ldo + n0 + half * 64;
#pragma unroll
        for (int v = 0; v < 8; ++v) {
            uint32_t hw[4], lw[4];
#pragma unroll
            for (int q = 0; q < 4; ++q) {
                float x0 = stg[row * 132 + half * 64 + v * 8 + q * 2];
                float x1 = stg[row * 132 + half * 64 + v * 8 + q * 2 + 1];
                fp16 h0, l0, h1, l1;
                split2h(x0, h0, l0); split2h(x1, h1, l1);
                __half2 hp = __halves2half2(h0, h1), lp = __halves2half2(l0, l1);
                hw[q] = *(uint32_t*)&hp; lw[q] = *(uint32_t*)&lp;
            }
            *(uint4*)(oH + base + v * 8) = make_uint4(hw[0], hw[1], hw[2], hw[3]);
            if (oL) *(uint4*)(oL + base + v * 8) = make_uint4(lw[0], lw[1], lw[2], lw[3]);
        }
    } else if (EPI == 2) {
        const int n = row, mh = half * 64;
        const size_t base = (size_t)z * sO + (size_t)(n0 + n) * ldo + m0 + mh;
#pragma unroll
        for (int v = 0; v < 8; ++v) {
            uint32_t hw[4], lw[4];
#pragma unroll
            for (int q = 0; q < 4; ++q) {
                float x0 = stg[(mh + v * 8 + q * 2) * 132 + n];
                float x1 = stg[(mh + v * 8 + q * 2 + 1) * 132 + n];
                fp16 h0, l0, h1, l1;
                split2h(x0, h0, l0); split2h(x1, h1, l1);
                __half2 hp = __halves2half2(h0, h1), lp = __halves2half2(l0, l1);
                hw[q] = *(uint32_t*)&hp; lw[q] = *(uint32_t*)&lp;
            }
            *(uint4*)(oH + base + v * 8) = make_uint4(hw[0], hw[1], hw[2], hw[3]);
            if (oL) *(uint4*)(oL + base + v * 8) = make_uint4(lw[0], lw[1], lw[2], lw[3]);
        }
    } else {   // EPI == 3: E = exp(D - tile max) fp16 + stats
        const size_t base = (size_t)z * sO + (size_t)(m0 + row) * ldo + n0 + half * 64;
        const float* src = &stg[row * 132 + half * 64];
        float mx = -3.0e38f;
#pragma unroll
        for (int q = 0; q < 64; ++q) mx = fmaxf(mx, src[q]);
        mx = fmaxf(mx, __shfl_xor_sync(0xffffffffu, mx, 1));
        float s = 0.f;
#pragma unroll
        for (int v = 0; v < 8; ++v) {
            uint32_t w[4];
#pragma unroll
            for (int q = 0; q < 4; ++q) {
                float e0 = __expf(src[v * 8 + q * 2]     - mx);
                float e1 = __expf(src[v * 8 + q * 2 + 1] - mx);
                s += e0 + e1;
                __half2 hp = __floats2half2_rn(e0, e1);
                w[q] = *(uint32_t*)&hp;
            }
            *(uint4*)(oH + base + v * 8) = make_uint4(w[0], w[1], w[2], w[3]);
        }
        s += __shfl_xor_sync(0xffffffffu, s, 1);
        if (half == 0) {
            size_t o = ((size_t)z * 32 + blockIdx.x) * NPIX + m0 + row;
            stM[o] = mx; stS[o] = s;
        }
    }
}

// ---------------------------------------------------------------------------
__global__ void __launch_bounds__(256)
combine_stats(const float* __restrict__ stM, const float* __restrict__ stS,
              float* __restrict__ rowM, float* __restrict__ rowIL)
{
    const int idx = blockIdx.x * 256 + threadIdx.x;
    if (idx >= BATCH * NPIX) return;
    const int z = idx >> 12, i = idx & (NPIX - 1);
    float m = -3.0e38f;
#pragma unroll 4
    for (int t = 0; t < 32; ++t)
        m = fmaxf(m, stM[((size_t)z * 32 + t) * NPIX + i]);
    float l = 0.f;
#pragma unroll 4
    for (int t = 0; t < 32; ++t) {
        size_t o = ((size_t)z * 32 + t) * NPIX + i;
        l += stS[o] * __expf(stM[o] - m);
    }
    rowM[idx] = m;
    rowIL[idx] = 1.0f / l;
}

// ---------------------------------------------------------------------------
__global__ void __launch_bounds__(256)
tsplit_both(const float* __restrict__ Fc, const float* __restrict__ Fs,
            fp16* __restrict__ ohc, fp16* __restrict__ olc,
            fp16* __restrict__ ohs, fp16* __restrict__ ols)
{
    __shared__ float t[32][33];
    const int zz = blockIdx.z;
    const int b = zz & 3;
    const float* X = (zz < 4) ? Fc : Fs;
    fp16* oh = (zz < 4) ? ohc : ohs;
    fp16* ol = (zz < 4) ? olc : ols;
    const int pb = blockIdx.x * 32, cb = blockIdx.y * 32;
    const float* src = X + (size_t)b * CDIM * NPIX;
#pragma unroll
    for (int j = 0; j < 4; ++j) {
        int c = cb + threadIdx.y + j * 8;
        t[threadIdx.y + j * 8][threadIdx.x] = src[(size_t)c * NPIX + pb + threadIdx.x];
    }
    __syncthreads();
#pragma unroll
    for (int j = 0; j < 4; ++j) {
        int p = pb + threadIdx.y + j * 8;
        float v = t[threadIdx.x][threadIdx.y + j * 8];
        size_t o = (size_t)b * NPIX * CDIM + (size_t)p * CDIM + cb + threadIdx.x;
        fp16 h, l; split2h(v, h, l);
        oh[o] = h; ol[o] = l;
    }
}

__global__ void __launch_bounds__(256)
wsplit_all(const float* __restrict__ w0, const float* __restrict__ w1,
           const float* __restrict__ w2, const float* __restrict__ w3,
           fp16* __restrict__ h0, fp16* __restrict__ l0,
           fp16* __restrict__ h1, fp16* __restrict__ l1,
           fp16* __restrict__ h2, fp16* __restrict__ l2,
           fp16* __restrict__ h3, fp16* __restrict__ l3)
{
    const float* w = (blockIdx.y == 0) ? w0 : (blockIdx.y == 1) ? w1 : (blockIdx.y == 2) ? w2 : w3;
    fp16* hh = (blockIdx.y == 0) ? h0 : (blockIdx.y == 1) ? h1 : (blockIdx.y == 2) ? h2 : h3;
    fp16* ll = (blockIdx.y == 0) ? l0 : (blockIdx.y == 1) ? l1 : (blockIdx.y == 2) ? l2 : l3;
    int i = blockIdx.x * 256 + threadIdx.x;
    if (i < CDIM * CDIM) { fp16 a, b; split2h(w[i], a, b); hh[i] = a; ll[i] = b; }
}

// ---------------------------------------------------------------------------
extern "C" void kernel_launch(void* const* d_in, const int* in_sizes, int n_in,
                              void* d_out, int out_size)
{
    const float* F_c = (const float*)d_in[0];
    const float* F_s = (const float*)d_in[1];
    const float* w_f = (const float*)d_in[2];
    const float* b_f = (const float*)d_in[3];
    const float* w_g = (const float*)d_in[4];
    const float* b_g = (const float*)d_in[5];
    const float* w_h = (const float*)d_in[6];
    const float* b_h = (const float*)d_in[7];
    const float* w_o = (const float*)d_in[8];
    const float* b_o = (const float*)d_in[9];
    float* out = (float*)d_out;

    fp16 *FcTh, *FcTl, *FsTh, *FsTl, *wfh, *wfl, *wgh, *wgl, *whh, *whl, *woh, *wol;
    fp16 *Fqh, *Fql, *Gh, *Gl, *Hvh, *Rh, *E;
    float *stM, *stS, *rowM, *rowIL;
    cudaGetSymbolAddress((void**)&FcTh, g_FcT_h); cudaGetSymbolAddress((void**)&FcTl, g_FcT_l);
    cudaGetSymbolAddress((void**)&FsTh, g_FsT_h); cudaGetSymbolAddress((void**)&FsTl, g_FsT_l);
    cudaGetSymbolAddress((void**)&wfh, g_wf_h);   cudaGetSymbolAddress((void**)&wfl, g_wf_l);
    cudaGetSymbolAddress((void**)&wgh, g_wg_h);   cudaGetSymbolAddress((void**)&wgl, g_wg_l);
    cudaGetSymbolAddress((void**)&whh, g_wh_h);   cudaGetSymbolAddress((void**)&whl, g_wh_l);
    cudaGetSymbolAddress((void**)&woh, g_wo_h);   cudaGetSymbolAddress((void**)&wol, g_wo_l);
    cudaGetSymbolAddress((void**)&Fqh, g_Fq_h);   cudaGetSymbolAddress((void**)&Fql, g_Fq_l);
    cudaGetSymbolAddress((void**)&Gh,  g_G_h);    cudaGetSymbolAddress((void**)&Gl,  g_G_l);
    cudaGetSymbolAddress((void**)&Hvh, g_Hv_h);   cudaGetSymbolAddress((void**)&Rh,  g_R_h);
    cudaGetSymbolAddress((void**)&E,   g_E);
    cudaGetSymbolAddress((void**)&stM, g_stM);    cudaGetSymbolAddress((void**)&stS, g_stS);
    cudaGetSymbolAddress((void**)&rowM, g_rowM);  cudaGetSymbolAddress((void**)&rowIL, g_rowIL);

    cudaFuncSetAttribute((const void*)mma_gemm<2,false,3,false,2>, cudaFuncAttributeMaxDynamicSharedMemorySize, DSMEM);
    cudaFuncSetAttribute((const void*)mma_gemm<3,false,3,true ,1>, cudaFuncAttributeMaxDynamicSharedMemorySize, DSMEM);
    cudaFuncSetAttribute((const void*)mma_gemm<1,false,2,false,2>, cudaFuncAttributeMaxDynamicSharedMemorySize, DSMEM);
    cudaFuncSetAttribute((const void*)mma_gemm<0,false,2,false,2>, cudaFuncAttributeMaxDynamicSharedMemorySize, DSMEM);
    cudaFuncSetAttribute((const void*)mma_gemm<2,true ,1,false,2>, cudaFuncAttributeMaxDynamicSharedMemorySize, DSMEM_F);

    const long long cn = (long long)NPIX * CDIM;
    const long long nn = (long long)NPIX * NPIX;

    dim3 gConv(NPIX / 128, CDIM / 128, BATCH);   // 32 x 2 x 4
    dim3 gS(NPIX / 128, NPIX / 128, BATCH);      // 32 x 32 x 4

    // L1, L2: conversions
    wsplit_all<<<dim3(256, 4), 256>>>(w_f, w_g, w_h, w_o,
        wfh, wfl, wgh, wgl, whh, whl, woh, wol);
    tsplit_both<<<dim3(128, 8, 8), dim3(32, 8)>>>(F_c, F_s, FcTh, FcTl, FsTh, FsTl);
    // L3 (G1): Fq_t (3-pass, fp32 acc, 2-CTA)
    mma_gemm<2,false,3,false,2><<<gConv, 256, DSMEM>>>(wfh, wfl, FcTh, FcTl,
        CDIM, CDIM, CDIM, CDIM, 0, cn, cn, b_f, nullptr, Fqh, Fql,
        nullptr, nullptr, nullptr, nullptr, nullptr);
    // L4 (G2): G_t
    mma_gemm<2,false,3,false,2><<<gConv, 256, DSMEM>>>(wgh, wgl, FsTh, FsTl,
        CDIM, CDIM, CDIM, CDIM, 0, cn, cn, b_g, nullptr, Gh, Gl,
        nullptr, nullptr, nullptr, nullptr, nullptr);
    // L5 (G4): E + stats (3-pass, HACC corrections) — ncu target
    mma_gemm<3,false,3,true,1><<<gS, 256, DSMEM>>>(Fqh, Fql, Gh, Gl,
        CDIM, CDIM, CDIM, NPIX, cn, cn, nn, nullptr, nullptr, E, nullptr,
        nullptr, nullptr, nullptr, stM, stS);
    // L6 (G3): Hv hi only (2-pass)
    mma_gemm<1,false,2,false,2><<<gConv, 256, DSMEM>>>(whh, whl, FsTh, nullptr,
        CDIM, CDIM, CDIM, NPIX, 0, cn, cn, b_h, nullptr, Hvh, nullptr,
        nullptr, nullptr, nullptr, nullptr, nullptr);
    // L7: stats fold
    combine_stats<<<(BATCH * NPIX + 255) / 256, 256>>>(stM, stS, rowM, rowIL);
    // L8 (G5): R_t hi only (1-pass, FUSEB from fp16 E)
    mma_gemm<2,true,1,false,2><<<gConv, 256, DSMEM_F>>>(Hvh, nullptr, nullptr, nullptr,
        NPIX, NPIX, NPIX, CDIM, cn, nn, cn, nullptr, nullptr, Rh, nullptr,
        E, rowM, rowIL, stM, nullptr);
    // L9 (G6): out = w_o @ R + b_o (2-pass)
    mma_gemm<0,false,2,false,2><<<gConv, 256, DSMEM>>>(woh, wol, Rh, nullptr,
        CDIM, CDIM, CDIM, NPIX, 0, cn, cn, b_o, out, nullptr, nullptr,
        nullptr, nullptr, nullptr, nullptr, nullptr);
}